// round 3
// baseline (speedup 1.0000x reference)
#include <cuda_runtime.h>
#include <cstdint>

#define NN 25000
#define NE 400000
#define FEAT 128
#define HID 64
#define HEADS 4
#define NCLS 2
#define NGRAPH 64

// ---------------- scratch (device globals; no allocation) ----------------
__device__ alignas(16) float g_xr1 [NN * 64];          // rel-transformed (reused conv1/conv5)
__device__ alignas(16) float g_acc1[NN * 64];          // root-transform + bias, then +=agg
__device__ alignas(16) float g_xl  [(size_t)NN * 256]; // GAT transformed feats, later h2
__device__ alignas(16) float g_S   [(size_t)NN * 256]; // GAT unnormalized weighted sum
__device__ alignas(16) float g_as  [NN * 4];
__device__ alignas(16) float g_ad  [NN * 4];
__device__ alignas(16) float g_mf  [NN * 4];
__device__ alignas(16) float g_den [NN * 4];
__device__ alignas(16) unsigned g_menc[NN * 4];
__device__ alignas(16) float g_pool[NGRAPH * HID];

// ---------------- helpers ----------------
__device__ __forceinline__ float lrelu(float x) { return x > 0.f ? x : 0.2f * x; }

__device__ __forceinline__ unsigned fenc(float f) {
    unsigned u = __float_as_uint(f);
    return (u & 0x80000000u) ? ~u : (u | 0x80000000u);
}
__device__ __forceinline__ float fdec(unsigned u) {
    return __uint_as_float((u & 0x80000000u) ? (u & 0x7fffffffu) : ~u);
}

__device__ __forceinline__ void red4(float* p, float4 v) {
    asm volatile("red.global.add.v4.f32 [%0], {%1,%2,%3,%4};"
                 :: "l"(p), "f"(v.x), "f"(v.y), "f"(v.z), "f"(v.w) : "memory");
}

__device__ __forceinline__ unsigned long long packdup(float b) {
    unsigned long long r;
    asm("mov.b64 %0, {%1, %1};" : "=l"(r) : "f"(b));
    return r;
}
__device__ __forceinline__ void ffma2(unsigned long long& acc, unsigned long long a,
                                      unsigned long long b) {
    asm("fma.rn.f32x2 %0, %1, %2, %0;" : "+l"(acc) : "l"(a), "l"(b));
}
__device__ __forceinline__ void unpack2(unsigned long long v, float& lo, float& hi) {
    unsigned a, b;
    asm("mov.b64 {%0, %1}, %2;" : "=r"(a), "=r"(b) : "l"(v));
    lo = __uint_as_float(a); hi = __uint_as_float(b);
}

// ============ 128x128-tile SGEMM with packed f32x2 FMAs ============
// C[M, Ncols] = act(A[M,K]) @ B[K,Ncols] (+bias on the C1 half)
// Split mode (B1 != null): B = [B0 | B1] each K x 64 (ldb stride), output
//   cols 0..63 -> C0 (ldc=64), cols 64..127 -> C1 (+bias1).
// Contiguous mode (B1 == null): B0 is K x N (ldb), C0 with stride ldc,
//   col block selected by blockIdx.x.
__global__ __launch_bounds__(256, 2)
void gemm128_kernel(const float* __restrict__ A, int lda, int K,
                    const float* __restrict__ B0, const float* __restrict__ B1, int ldb,
                    float* __restrict__ C0, float* __restrict__ C1, int ldc,
                    int M, const float* __restrict__ bias1, int reluA)
{
    __shared__ alignas(16) float As[16][132];   // transposed A tile (k-major)
    __shared__ alignas(16) float Bs[16][128];

    int tid = threadIdx.x;
    int row0 = blockIdx.y * 128;
    int col0 = blockIdx.x * 128;          // nonzero only in contiguous mode
    int ty = tid >> 4, tx = tid & 15;

    int ar = tid >> 1;                    // A tile row 0..127
    int ak = (tid & 1) * 8;               // A tile k-offset 0 or 8
    int bk = tid >> 4;                    // B tile k-row 0..15
    int bc = (tid & 15) * 8;              // B tile col 0..120

    unsigned long long acc[4][8];
#pragma unroll
    for (int i = 0; i < 4; i++)
#pragma unroll
        for (int j = 0; j < 8; j++) acc[i][j] = 0ULL;

    for (int k0 = 0; k0 < K; k0 += 16) {
        // ---- load A tile (transposed into As) ----
        float av[8];
        int r = row0 + ar;
        if (r < M) {
            const float* ap = A + (size_t)r * lda + k0 + ak;
            float4 t0 = *(const float4*)ap;
            float4 t1 = *(const float4*)(ap + 4);
            av[0] = t0.x; av[1] = t0.y; av[2] = t0.z; av[3] = t0.w;
            av[4] = t1.x; av[5] = t1.y; av[6] = t1.z; av[7] = t1.w;
        } else {
#pragma unroll
            for (int j = 0; j < 8; j++) av[j] = 0.f;
        }
        if (reluA) {
#pragma unroll
            for (int j = 0; j < 8; j++) av[j] = fmaxf(av[j], 0.f);
        }
#pragma unroll
        for (int j = 0; j < 8; j++) As[ak + j][ar] = av[j];

        // ---- load B tile ----
        const float* bp;
        if (B1) bp = (bc < 64) ? (B0 + (size_t)(k0 + bk) * ldb + bc)
                               : (B1 + (size_t)(k0 + bk) * ldb + bc - 64);
        else    bp = B0 + (size_t)(k0 + bk) * ldb + col0 + bc;
        *(float4*)&Bs[bk][bc]     = *(const float4*)bp;
        *(float4*)&Bs[bk][bc + 4] = *(const float4*)(bp + 4);
        __syncthreads();

#pragma unroll
        for (int k = 0; k < 16; k++) {
            ulonglong2 pa0 = *(const ulonglong2*)&As[k][ty * 8];
            ulonglong2 pa1 = *(const ulonglong2*)&As[k][ty * 8 + 4];
            unsigned long long a2[4] = {pa0.x, pa0.y, pa1.x, pa1.y};
            float4 fb0 = *(const float4*)&Bs[k][tx * 8];
            float4 fb1 = *(const float4*)&Bs[k][tx * 8 + 4];
            unsigned long long b2[8];
            b2[0] = packdup(fb0.x); b2[1] = packdup(fb0.y);
            b2[2] = packdup(fb0.z); b2[3] = packdup(fb0.w);
            b2[4] = packdup(fb1.x); b2[5] = packdup(fb1.y);
            b2[6] = packdup(fb1.z); b2[7] = packdup(fb1.w);
#pragma unroll
            for (int rp = 0; rp < 4; rp++)
#pragma unroll
                for (int c = 0; c < 8; c++)
                    ffma2(acc[rp][c], a2[rp], b2[c]);
        }
        __syncthreads();
    }

    // ---- epilogue ----
#pragma unroll
    for (int rp = 0; rp < 4; rp++) {
        int r0 = row0 + ty * 8 + rp * 2;
#pragma unroll
        for (int c = 0; c < 8; c++) {
            float lo, hi;
            unpack2(acc[rp][c], lo, hi);
            int col = col0 + tx * 8 + c;
            if (C1 && (tx * 8 + c) >= 64) {
                int cc = tx * 8 + c - 64;
                float bv = bias1 ? bias1[cc] : 0.f;
                if (r0 < M)     C1[(size_t)r0 * ldc + cc] = lo + bv;
                if (r0 + 1 < M) C1[(size_t)(r0 + 1) * ldc + cc] = hi + bv;
            } else {
                if (r0 < M)     C0[(size_t)r0 * ldc + col] = lo;
                if (r0 + 1 < M) C0[(size_t)(r0 + 1) * ldc + col] = hi;
            }
        }
    }
}

// ---------------- conv edge scatter: g_acc1[dst] += g_xr1[src]  (64-dim) ----------------
__global__ void conv_edge_kernel(const int* __restrict__ src, const int* __restrict__ dst)
{
    int tid = blockIdx.x * 256 + threadIdx.x;
    int e = tid >> 4, t = tid & 15;
    if (e >= NE) return;
    int s = src[e], d = dst[e];
    float4 v = *(const float4*)(g_xr1 + (size_t)s * 64 + t * 4);
    red4(g_acc1 + (size_t)d * 64 + t * 4, v);
}

// ---------------- attention prep: a_s, a_d, init max with self-loop ----------------
__global__ void att_prep_kernel(const float* __restrict__ att_src, const float* __restrict__ att_dst)
{
    __shared__ float s_as[256], s_ad[256];
    int tid = threadIdx.x;
    if (tid < 256) { s_as[tid] = att_src[tid]; s_ad[tid] = att_dst[tid]; }
    __syncthreads();
    int warp = tid >> 5, lane = tid & 31;
    int n = blockIdx.x * 8 + warp;
    if (n >= NN) return;
    const float* xr = g_xl + (size_t)n * 256;
    float vs[4], vd[4];
#pragma unroll
    for (int h = 0; h < 4; h++) {
        float x0 = xr[h * 64 + lane], x1 = xr[h * 64 + lane + 32];
        float ps = x0 * s_as[h * 64 + lane] + x1 * s_as[h * 64 + lane + 32];
        float pd = x0 * s_ad[h * 64 + lane] + x1 * s_ad[h * 64 + lane + 32];
#pragma unroll
        for (int off = 16; off; off >>= 1) {
            ps += __shfl_down_sync(0xffffffffu, ps, off);
            pd += __shfl_down_sync(0xffffffffu, pd, off);
        }
        vs[h] = ps; vd[h] = pd;
    }
    if (lane == 0) {
#pragma unroll
        for (int h = 0; h < 4; h++) {
            g_as[n * 4 + h] = vs[h];
            g_ad[n * 4 + h] = vd[h];
            g_menc[n * 4 + h] = fenc(lrelu(vs[h] + vd[h]));   // self-loop seed
        }
    }
}

// ---------------- edge max pass ----------------
__global__ void edge_max_kernel(const int* __restrict__ src, const int* __restrict__ dst)
{
    int e = blockIdx.x * 256 + threadIdx.x;
    if (e >= NE) return;
    int s = src[e], d = dst[e];
    float4 a = *(const float4*)(g_as + s * 4);
    float4 b = *(const float4*)(g_ad + d * 4);
    float av[4] = {a.x, a.y, a.z, a.w}, bv[4] = {b.x, b.y, b.z, b.w};
#pragma unroll
    for (int h = 0; h < 4; h++)
        atomicMax(&g_menc[d * 4 + h], fenc(lrelu(av[h] + bv[h])));
}

// ---------------- init S/denom with self-loop contribution ----------------
__global__ void init_S_kernel()
{
    int idx = blockIdx.x * 256 + threadIdx.x;
    int n = idx >> 8, c = idx & 255, h = c >> 6;
    float mf = fdec(g_menc[n * 4 + h]);
    float es = lrelu(g_as[n * 4 + h] + g_ad[n * 4 + h]);
    float p = expf(es - mf);
    g_S[idx] = p * g_xl[idx];
    if (c < 4) {
        float mfh = fdec(g_menc[n * 4 + c]);
        g_mf[n * 4 + c] = mfh;
        float e2 = lrelu(g_as[n * 4 + c] + g_ad[n * 4 + c]);
        g_den[n * 4 + c] = expf(e2 - mfh);
    }
}

// ---------------- GAT edge pass 2: S[dst] += p*xl[src], denom[dst] += p ----------------
__global__ void gat_edge_kernel(const int* __restrict__ src, const int* __restrict__ dst)
{
    int gt = blockIdx.x * 256 + threadIdx.x;
    int e = gt >> 5, lane = gt & 31;
    if (e >= NE) return;
    int s = src[e], d = dst[e];
    float asv = (lane < 4) ? g_as[s * 4 + lane] : 0.f;
    float adv = (lane < 4) ? g_ad[d * 4 + lane] : 0.f;
    float mv  = (lane < 4) ? g_mf[d * 4 + lane] : 0.f;

    int h1 = lane >> 4;            // 0 or 1
    int h2 = 2 + (lane >> 4);      // 2 or 3
    int hd = lane & 3;             // head for denom-lane

    float e1 = lrelu(__shfl_sync(0xffffffffu, asv, h1) + __shfl_sync(0xffffffffu, adv, h1));
    float m1 = __shfl_sync(0xffffffffu, mv, h1);
    float e2 = lrelu(__shfl_sync(0xffffffffu, asv, h2) + __shfl_sync(0xffffffffu, adv, h2));
    float m2 = __shfl_sync(0xffffffffu, mv, h2);
    float ed = lrelu(__shfl_sync(0xffffffffu, asv, hd) + __shfl_sync(0xffffffffu, adv, hd));
    float md = __shfl_sync(0xffffffffu, mv, hd);

    float p1 = expf(e1 - m1);
    float p2 = expf(e2 - m2);
    float pd = expf(ed - md);

    const float* xr = g_xl + (size_t)s * 256;
    float* Sd = g_S + (size_t)d * 256;
    float4 v1 = *(const float4*)(xr + lane * 4);
    float4 v2 = *(const float4*)(xr + 128 + lane * 4);
    red4(Sd + lane * 4,       make_float4(p1 * v1.x, p1 * v1.y, p1 * v1.z, p1 * v1.w));
    red4(Sd + 128 + lane * 4, make_float4(p2 * v2.x, p2 * v2.y, p2 * v2.z, p2 * v2.w));
    if (lane < 4) atomicAdd(&g_den[d * 4 + lane], pd);
}

// ---------------- h2 = relu(S/denom + bg), written into g_xl ----------------
__global__ void h2_kernel(const float* __restrict__ bg)
{
    int idx = blockIdx.x * 256 + threadIdx.x;
    int n = idx >> 8, c = idx & 255, h = c >> 6;
    float v = g_S[idx] / g_den[n * 4 + h] + bg[c];
    g_xl[idx] = fmaxf(v, 0.f);
}

// ---------------- zero pool ----------------
__global__ void zero_pool_kernel()
{
    int t = blockIdx.x * 256 + threadIdx.x;
    if (t < NGRAPH * HID) g_pool[t] = 0.f;
}

// ---------------- pooling: g_pool[batch[n]] += relu(acc5[n])  (batch sorted) ----------------
__global__ void pool_kernel(const int* __restrict__ batch)
{
    int d = threadIdx.x & 63;
    int sub = threadIdx.x >> 6;
    int n0 = blockIdx.x * 64 + sub * 16;
    float sum = 0.f; int cur = -1;
#pragma unroll
    for (int i = 0; i < 16; i++) {
        int n = n0 + i;
        if (n >= NN) break;
        int b = batch[n];
        if (b != cur) {
            if (cur >= 0) atomicAdd(&g_pool[cur * 64 + d], sum);
            cur = b; sum = 0.f;
        }
        sum += fmaxf(g_acc1[(size_t)n * 64 + d], 0.f);
    }
    if (cur >= 0) atomicAdd(&g_pool[cur * 64 + d], sum);
}

// ---------------- head: relu(pool@Wfc1+b) @ Wfc2 + b -> sigmoid ----------------
__global__ void head_kernel(const float* __restrict__ Wfc1, const float* __restrict__ bfc1,
                            const float* __restrict__ Wfc2, const float* __restrict__ bfc2,
                            float* __restrict__ out)
{
    __shared__ float sg[64 * 64];
    __shared__ float sw[64 * 64];
    int t = threadIdx.x;
    for (int i = t; i < 4096; i += 256) { sg[i] = g_pool[i]; sw[i] = Wfc1[i]; }
    __syncthreads();
    float r[16];
#pragma unroll
    for (int i = 0; i < 16; i++) {
        int idx = t + 256 * i;
        int rr = idx >> 6, cc = idx & 63;
        float s = bfc1[cc];
#pragma unroll
        for (int k = 0; k < 64; k++) s += sg[rr * 64 + k] * sw[k * 64 + cc];
        r[i] = fmaxf(s, 0.f);
    }
    __syncthreads();
#pragma unroll
    for (int i = 0; i < 16; i++) sg[t + 256 * i] = r[i];
    __syncthreads();
    if (t < 128) {
        int rr = t >> 1, cc = t & 1;
        float s = bfc2[cc];
#pragma unroll
        for (int k = 0; k < 64; k++) s += sg[rr * 64 + k] * Wfc2[k * 2 + cc];
        out[t] = 1.f / (1.f + expf(-s));
    }
}

// ---------------- launch ----------------
extern "C" void kernel_launch(void* const* d_in, const int* in_sizes, int n_in,
                              void* d_out, int out_size)
{
    const float* x       = (const float*)d_in[0];
    const int*   ei      = (const int*)d_in[1];
    const int*   batch   = (const int*)d_in[2];
    const float* W1_rel  = (const float*)d_in[3];
    const float* b1      = (const float*)d_in[4];
    const float* W1_root = (const float*)d_in[5];
    const float* Wg      = (const float*)d_in[6];
    const float* att_src = (const float*)d_in[7];
    const float* att_dst = (const float*)d_in[8];
    const float* bg      = (const float*)d_in[9];
    const float* W5_rel  = (const float*)d_in[10];
    const float* b5      = (const float*)d_in[11];
    const float* W5_root = (const float*)d_in[12];
    const float* W_fc1   = (const float*)d_in[13];
    const float* b_fc1   = (const float*)d_in[14];
    const float* W_fc2   = (const float*)d_in[15];
    const float* b_fc2   = (const float*)d_in[16];
    float* out = (float*)d_out;

    const int* src = ei;
    const int* dst = ei + NE;

    static float *p_xr1 = nullptr, *p_acc1 = nullptr, *p_xl = nullptr;
    if (!p_xr1) {
        cudaGetSymbolAddress((void**)&p_xr1, g_xr1);
        cudaGetSymbolAddress((void**)&p_acc1, g_acc1);
        cudaGetSymbolAddress((void**)&p_xl, g_xl);
    }

    const int GY = (NN + 127) / 128;   // 196

    zero_pool_kernel<<<16, 256>>>();

    // conv1 fused: [xr1 | acc1] = x @ [W1_rel | W1_root(+b1)]
    gemm128_kernel<<<dim3(1, GY), 256>>>(x, FEAT, FEAT, W1_rel, W1_root, 64,
                                         p_xr1, p_acc1, 64, NN, b1, 0);
    conv_edge_kernel<<<(NE * 16 + 255) / 256, 256>>>(src, dst);

    // GAT: xl = relu(h1) @ Wg   (N=256, contiguous)
    gemm128_kernel<<<dim3(2, GY), 256>>>(p_acc1, 64, 64, Wg, nullptr, 256,
                                         p_xl, nullptr, 256, NN, nullptr, 1);
    att_prep_kernel<<<(NN + 7) / 8, 256>>>(att_src, att_dst);
    edge_max_kernel<<<(NE + 255) / 256, 256>>>(src, dst);
    init_S_kernel<<<NN, 256>>>();
    gat_edge_kernel<<<(NE * 32 + 255) / 256, 256>>>(src, dst);
    h2_kernel<<<NN, 256>>>(bg);

    // conv5 fused: [xr5 | acc5] = h2 @ [W5_rel | W5_root(+b5)]
    gemm128_kernel<<<dim3(1, GY), 256>>>(p_xl, 256, 256, W5_rel, W5_root, 64,
                                         p_xr1, p_acc1, 64, NN, b5, 0);
    conv_edge_kernel<<<(NE * 16 + 255) / 256, 256>>>(src, dst);

    // pool + head
    pool_kernel<<<(NN + 63) / 64, 256>>>(batch);
    head_kernel<<<1, 256>>>(W_fc1, b_fc1, W_fc2, b_fc2, out);
}

// round 4
// speedup vs baseline: 1.0139x; 1.0139x over previous
#include <cuda_runtime.h>
#include <cstdint>

#define NN 25000
#define NE 400000
#define FEAT 128
#define HID 64
#define HEADS 4
#define NCLS 2
#define NGRAPH 64

// ---------------- scratch (device globals; no allocation) ----------------
__device__ alignas(16) float g_xr1 [NN * 64];          // rel-transformed (reused conv1/conv5)
__device__ alignas(16) float g_acc1[NN * 64];          // root-transform + bias, then +=agg
__device__ alignas(16) float g_xl  [(size_t)NN * 256]; // GAT transformed feats, later h2
__device__ alignas(16) float g_S   [(size_t)NN * 256]; // GAT unnormalized weighted sum
__device__ alignas(16) float g_as  [NN * 4];
__device__ alignas(16) float g_ad  [NN * 4];
__device__ alignas(16) float g_mf  [NN * 4];
__device__ alignas(16) float g_den [NN * 4];
__device__ alignas(16) unsigned g_menc[NN * 4];
__device__ alignas(16) float g_pool[NGRAPH * HID];

// ---------------- helpers ----------------
__device__ __forceinline__ float lrelu(float x) { return x > 0.f ? x : 0.2f * x; }

__device__ __forceinline__ unsigned fenc(float f) {
    unsigned u = __float_as_uint(f);
    return (u & 0x80000000u) ? ~u : (u | 0x80000000u);
}
__device__ __forceinline__ float fdec(unsigned u) {
    return __uint_as_float((u & 0x80000000u) ? (u & 0x7fffffffu) : ~u);
}

__device__ __forceinline__ void red4(float* p, float4 v) {
    asm volatile("red.global.add.v4.f32 [%0], {%1,%2,%3,%4};"
                 :: "l"(p), "f"(v.x), "f"(v.y), "f"(v.z), "f"(v.w) : "memory");
}

__device__ __forceinline__ unsigned long long packdup(float b) {
    unsigned long long r;
    asm("mov.b64 %0, {%1, %1};" : "=l"(r) : "f"(b));
    return r;
}
__device__ __forceinline__ void ffma2(unsigned long long& acc, unsigned long long a,
                                      unsigned long long b) {
    asm("fma.rn.f32x2 %0, %1, %2, %0;" : "+l"(acc) : "l"(a), "l"(b));
}
__device__ __forceinline__ void unpack2(unsigned long long v, float& lo, float& hi) {
    unsigned a, b;
    asm("mov.b64 {%0, %1}, %2;" : "=r"(a), "=r"(b) : "l"(v));
    lo = __uint_as_float(a); hi = __uint_as_float(b);
}

// ============ 128x128-tile SGEMM, double-buffered, packed f32x2 FMAs ============
// C = act(A[M,K]) @ B[K,*] (+bias on the C1 half)
// Split mode (B1 != null): B = [B0 | B1] each K x 64 (stride ldb); cols 0..63 -> C0,
//   cols 64..127 -> C1 (+bias1), both ldc.
// Contiguous mode (B1 == null): B0 is K x N (ldb); col block = blockIdx.x.
__global__ __launch_bounds__(256, 2)
void gemm128_kernel(const float* __restrict__ A, int lda, int K,
                    const float* __restrict__ B0, const float* __restrict__ B1, int ldb,
                    float* __restrict__ C0, float* __restrict__ C1, int ldc,
                    int M, const float* __restrict__ bias1, int reluA)
{
    __shared__ alignas(16) float As[2][16][132];   // transposed A tile (k-major)
    __shared__ alignas(16) float Bs[2][16][128];

    int tid = threadIdx.x;
    int row0 = blockIdx.y * 128;
    int col0 = blockIdx.x * 128;
    int ty = tid >> 4, tx = tid & 15;

    int ar = tid >> 1;                    // A tile row 0..127
    int ak = (tid & 1) * 8;               // A tile k-offset 0 or 8
    int bk = tid >> 4;                    // B tile k-row 0..15
    int bc = (tid & 15) * 8;              // B tile col 0..120

    int r = row0 + ar;
    bool aValid = (r < M);
    const float* aPtr = A + (size_t)(aValid ? r : 0) * lda + ak;
    const float* bPtr;
    if (B1) bPtr = (bc < 64) ? (B0 + (size_t)bk * ldb + bc)
                             : (B1 + (size_t)bk * ldb + bc - 64);
    else    bPtr = B0 + (size_t)bk * ldb + col0 + bc;
    size_t bStep = (size_t)16 * ldb;

    unsigned long long acc[4][8];
#pragma unroll
    for (int i = 0; i < 4; i++)
#pragma unroll
        for (int j = 0; j < 8; j++) acc[i][j] = 0ULL;

    float av[8], bv[8];
    // ---- prologue: load tile 0 into regs ----
    {
        float4 t0 = *(const float4*)aPtr;
        float4 t1 = *(const float4*)(aPtr + 4);
        av[0]=t0.x; av[1]=t0.y; av[2]=t0.z; av[3]=t0.w;
        av[4]=t1.x; av[5]=t1.y; av[6]=t1.z; av[7]=t1.w;
        float4 u0 = *(const float4*)bPtr;
        float4 u1 = *(const float4*)(bPtr + 4);
        bv[0]=u0.x; bv[1]=u0.y; bv[2]=u0.z; bv[3]=u0.w;
        bv[4]=u1.x; bv[5]=u1.y; bv[6]=u1.z; bv[7]=u1.w;
    }
    if (!aValid) {
#pragma unroll
        for (int j = 0; j < 8; j++) av[j] = 0.f;
    }
    if (reluA) {
#pragma unroll
        for (int j = 0; j < 8; j++) av[j] = fmaxf(av[j], 0.f);
    }
#pragma unroll
    for (int j = 0; j < 8; j++) As[0][ak + j][ar] = av[j];
    *(float4*)&Bs[0][bk][bc]     = make_float4(bv[0], bv[1], bv[2], bv[3]);
    *(float4*)&Bs[0][bk][bc + 4] = make_float4(bv[4], bv[5], bv[6], bv[7]);
    __syncthreads();

    int T = K >> 4;
    for (int t = 0; t < T; t++) {
        int cur = t & 1, nxt = cur ^ 1;
        bool more = (t + 1 < T);
        // ---- issue next-tile loads (latency overlapped with compute) ----
        if (more) {
            const float* ap = aPtr + (t + 1) * 16;
            float4 t0 = *(const float4*)ap;
            float4 t1 = *(const float4*)(ap + 4);
            av[0]=t0.x; av[1]=t0.y; av[2]=t0.z; av[3]=t0.w;
            av[4]=t1.x; av[5]=t1.y; av[6]=t1.z; av[7]=t1.w;
            const float* bp = bPtr + (size_t)(t + 1) * bStep;
            float4 u0 = *(const float4*)bp;
            float4 u1 = *(const float4*)(bp + 4);
            bv[0]=u0.x; bv[1]=u0.y; bv[2]=u0.z; bv[3]=u0.w;
            bv[4]=u1.x; bv[5]=u1.y; bv[6]=u1.z; bv[7]=u1.w;
        }

        // ---- compute 16 k-steps on current buffer ----
#pragma unroll
        for (int k = 0; k < 16; k++) {
            ulonglong2 pa0 = *(const ulonglong2*)&As[cur][k][ty * 8];
            ulonglong2 pa1 = *(const ulonglong2*)&As[cur][k][ty * 8 + 4];
            unsigned long long a2[4] = {pa0.x, pa0.y, pa1.x, pa1.y};
            float4 fb0 = *(const float4*)&Bs[cur][k][tx * 8];
            float4 fb1 = *(const float4*)&Bs[cur][k][tx * 8 + 4];
            unsigned long long b2[8];
            b2[0] = packdup(fb0.x); b2[1] = packdup(fb0.y);
            b2[2] = packdup(fb0.z); b2[3] = packdup(fb0.w);
            b2[4] = packdup(fb1.x); b2[5] = packdup(fb1.y);
            b2[6] = packdup(fb1.z); b2[7] = packdup(fb1.w);
#pragma unroll
            for (int rp = 0; rp < 4; rp++)
#pragma unroll
                for (int c = 0; c < 8; c++)
                    ffma2(acc[rp][c], a2[rp], b2[c]);
        }

        // ---- store next tile into the other buffer ----
        if (more) {
            if (!aValid) {
#pragma unroll
                for (int j = 0; j < 8; j++) av[j] = 0.f;
            }
            if (reluA) {
#pragma unroll
                for (int j = 0; j < 8; j++) av[j] = fmaxf(av[j], 0.f);
            }
#pragma unroll
            for (int j = 0; j < 8; j++) As[nxt][ak + j][ar] = av[j];
            *(float4*)&Bs[nxt][bk][bc]     = make_float4(bv[0], bv[1], bv[2], bv[3]);
            *(float4*)&Bs[nxt][bk][bc + 4] = make_float4(bv[4], bv[5], bv[6], bv[7]);
        }
        __syncthreads();
    }

    // ---- epilogue ----
#pragma unroll
    for (int rp = 0; rp < 4; rp++) {
        int r0 = row0 + ty * 8 + rp * 2;
#pragma unroll
        for (int c = 0; c < 8; c++) {
            float lo, hi;
            unpack2(acc[rp][c], lo, hi);
            int col = col0 + tx * 8 + c;
            if (C1 && (tx * 8 + c) >= 64) {
                int cc = tx * 8 + c - 64;
                float bvv = bias1 ? bias1[cc] : 0.f;
                if (r0 < M)     C1[(size_t)r0 * ldc + cc] = lo + bvv;
                if (r0 + 1 < M) C1[(size_t)(r0 + 1) * ldc + cc] = hi + bvv;
            } else {
                if (r0 < M)     C0[(size_t)r0 * ldc + col] = lo;
                if (r0 + 1 < M) C0[(size_t)(r0 + 1) * ldc + col] = hi;
            }
        }
    }
}

// ---------------- conv edge scatter: g_acc1[dst] += g_xr1[src]  (64-dim) ----------------
__global__ void conv_edge_kernel(const int* __restrict__ src, const int* __restrict__ dst)
{
    int tid = blockIdx.x * 256 + threadIdx.x;
    int e = tid >> 4, t = tid & 15;
    if (e >= NE) return;
    int s = src[e], d = dst[e];
    float4 v = *(const float4*)(g_xr1 + (size_t)s * 64 + t * 4);
    red4(g_acc1 + (size_t)d * 64 + t * 4, v);
}

// ---------------- attention prep: a_s, a_d, init max with self-loop ----------------
__global__ void att_prep_kernel(const float* __restrict__ att_src, const float* __restrict__ att_dst)
{
    __shared__ float s_as[256], s_ad[256];
    int tid = threadIdx.x;
    if (tid < 256) { s_as[tid] = att_src[tid]; s_ad[tid] = att_dst[tid]; }
    __syncthreads();
    int warp = tid >> 5, lane = tid & 31;
    int n = blockIdx.x * 8 + warp;
    if (n >= NN) return;
    const float* xr = g_xl + (size_t)n * 256;
    float vs[4], vd[4];
#pragma unroll
    for (int h = 0; h < 4; h++) {
        float x0 = xr[h * 64 + lane], x1 = xr[h * 64 + lane + 32];
        float ps = x0 * s_as[h * 64 + lane] + x1 * s_as[h * 64 + lane + 32];
        float pd = x0 * s_ad[h * 64 + lane] + x1 * s_ad[h * 64 + lane + 32];
#pragma unroll
        for (int off = 16; off; off >>= 1) {
            ps += __shfl_down_sync(0xffffffffu, ps, off);
            pd += __shfl_down_sync(0xffffffffu, pd, off);
        }
        vs[h] = ps; vd[h] = pd;
    }
    if (lane == 0) {
#pragma unroll
        for (int h = 0; h < 4; h++) {
            g_as[n * 4 + h] = vs[h];
            g_ad[n * 4 + h] = vd[h];
            g_menc[n * 4 + h] = fenc(lrelu(vs[h] + vd[h]));   // self-loop seed
        }
    }
}

// ---------------- edge max pass ----------------
__global__ void edge_max_kernel(const int* __restrict__ src, const int* __restrict__ dst)
{
    int e = blockIdx.x * 256 + threadIdx.x;
    if (e >= NE) return;
    int s = src[e], d = dst[e];
    float4 a = *(const float4*)(g_as + s * 4);
    float4 b = *(const float4*)(g_ad + d * 4);
    float av[4] = {a.x, a.y, a.z, a.w}, bv[4] = {b.x, b.y, b.z, b.w};
#pragma unroll
    for (int h = 0; h < 4; h++)
        atomicMax(&g_menc[d * 4 + h], fenc(lrelu(av[h] + bv[h])));
}

// ---------------- init S/denom with self-loop contribution ----------------
__global__ void init_S_kernel()
{
    int idx = blockIdx.x * 256 + threadIdx.x;
    int n = idx >> 8, c = idx & 255, h = c >> 6;
    float mf = fdec(g_menc[n * 4 + h]);
    float es = lrelu(g_as[n * 4 + h] + g_ad[n * 4 + h]);
    float p = expf(es - mf);
    g_S[idx] = p * g_xl[idx];
    if (c < 4) {
        float mfh = fdec(g_menc[n * 4 + c]);
        g_mf[n * 4 + c] = mfh;
        float e2 = lrelu(g_as[n * 4 + c] + g_ad[n * 4 + c]);
        g_den[n * 4 + c] = expf(e2 - mfh);
    }
}

// ---------------- GAT edge pass 2: S[dst] += p*xl[src], denom[dst] += p ----------------
__global__ void gat_edge_kernel(const int* __restrict__ src, const int* __restrict__ dst)
{
    int gt = blockIdx.x * 256 + threadIdx.x;
    int e = gt >> 5, lane = gt & 31;
    if (e >= NE) return;
    int s = src[e], d = dst[e];
    float asv = (lane < 4) ? g_as[s * 4 + lane] : 0.f;
    float adv = (lane < 4) ? g_ad[d * 4 + lane] : 0.f;
    float mv  = (lane < 4) ? g_mf[d * 4 + lane] : 0.f;

    int h1 = lane >> 4;            // 0 or 1
    int h2 = 2 + (lane >> 4);      // 2 or 3
    int hd = lane & 3;             // head for denom-lane

    float e1 = lrelu(__shfl_sync(0xffffffffu, asv, h1) + __shfl_sync(0xffffffffu, adv, h1));
    float m1 = __shfl_sync(0xffffffffu, mv, h1);
    float e2 = lrelu(__shfl_sync(0xffffffffu, asv, h2) + __shfl_sync(0xffffffffu, adv, h2));
    float m2 = __shfl_sync(0xffffffffu, mv, h2);
    float ed = lrelu(__shfl_sync(0xffffffffu, asv, hd) + __shfl_sync(0xffffffffu, adv, hd));
    float md = __shfl_sync(0xffffffffu, mv, hd);

    float p1 = expf(e1 - m1);
    float p2 = expf(e2 - m2);
    float pd = expf(ed - md);

    const float* xr = g_xl + (size_t)s * 256;
    float* Sd = g_S + (size_t)d * 256;
    float4 v1 = *(const float4*)(xr + lane * 4);
    float4 v2 = *(const float4*)(xr + 128 + lane * 4);
    red4(Sd + lane * 4,       make_float4(p1 * v1.x, p1 * v1.y, p1 * v1.z, p1 * v1.w));
    red4(Sd + 128 + lane * 4, make_float4(p2 * v2.x, p2 * v2.y, p2 * v2.z, p2 * v2.w));
    if (lane < 4) atomicAdd(&g_den[d * 4 + lane], pd);
}

// ---------------- h2 = relu(S/denom + bg), written into g_xl ----------------
__global__ void h2_kernel(const float* __restrict__ bg)
{
    int idx = blockIdx.x * 256 + threadIdx.x;
    int n = idx >> 8, c = idx & 255, h = c >> 6;
    float v = g_S[idx] / g_den[n * 4 + h] + bg[c];
    g_xl[idx] = fmaxf(v, 0.f);
}

// ---------------- zero pool ----------------
__global__ void zero_pool_kernel()
{
    int t = blockIdx.x * 256 + threadIdx.x;
    if (t < NGRAPH * HID) g_pool[t] = 0.f;
}

// ---------------- pooling: g_pool[batch[n]] += relu(acc5[n])  (batch sorted) ----------------
__global__ void pool_kernel(const int* __restrict__ batch)
{
    int d = threadIdx.x & 63;
    int sub = threadIdx.x >> 6;
    int n0 = blockIdx.x * 64 + sub * 16;
    float sum = 0.f; int cur = -1;
#pragma unroll
    for (int i = 0; i < 16; i++) {
        int n = n0 + i;
        if (n >= NN) break;
        int b = batch[n];
        if (b != cur) {
            if (cur >= 0) atomicAdd(&g_pool[cur * 64 + d], sum);
            cur = b; sum = 0.f;
        }
        sum += fmaxf(g_acc1[(size_t)n * 64 + d], 0.f);
    }
    if (cur >= 0) atomicAdd(&g_pool[cur * 64 + d], sum);
}

// ---------------- head: relu(pool@Wfc1+b) @ Wfc2 + b -> sigmoid ----------------
__global__ void head_kernel(const float* __restrict__ Wfc1, const float* __restrict__ bfc1,
                            const float* __restrict__ Wfc2, const float* __restrict__ bfc2,
                            float* __restrict__ out)
{
    __shared__ float sg[64 * 64];
    __shared__ float sw[64 * 64];
    int t = threadIdx.x;
    for (int i = t; i < 4096; i += 256) { sg[i] = g_pool[i]; sw[i] = Wfc1[i]; }
    __syncthreads();
    float r[16];
#pragma unroll
    for (int i = 0; i < 16; i++) {
        int idx = t + 256 * i;
        int rr = idx >> 6, cc = idx & 63;
        float s = bfc1[cc];
#pragma unroll
        for (int k = 0; k < 64; k++) s += sg[rr * 64 + k] * sw[k * 64 + cc];
        r[i] = fmaxf(s, 0.f);
    }
    __syncthreads();
#pragma unroll
    for (int i = 0; i < 16; i++) sg[t + 256 * i] = r[i];
    __syncthreads();
    if (t < 128) {
        int rr = t >> 1, cc = t & 1;
        float s = bfc2[cc];
#pragma unroll
        for (int k = 0; k < 64; k++) s += sg[rr * 64 + k] * Wfc2[k * 2 + cc];
        out[t] = 1.f / (1.f + expf(-s));
    }
}

// ---------------- launch ----------------
extern "C" void kernel_launch(void* const* d_in, const int* in_sizes, int n_in,
                              void* d_out, int out_size)
{
    const float* x       = (const float*)d_in[0];
    const int*   ei      = (const int*)d_in[1];
    const int*   batch   = (const int*)d_in[2];
    const float* W1_rel  = (const float*)d_in[3];
    const float* b1      = (const float*)d_in[4];
    const float* W1_root = (const float*)d_in[5];
    const float* Wg      = (const float*)d_in[6];
    const float* att_src = (const float*)d_in[7];
    const float* att_dst = (const float*)d_in[8];
    const float* bg      = (const float*)d_in[9];
    const float* W5_rel  = (const float*)d_in[10];
    const float* b5      = (const float*)d_in[11];
    const float* W5_root = (const float*)d_in[12];
    const float* W_fc1   = (const float*)d_in[13];
    const float* b_fc1   = (const float*)d_in[14];
    const float* W_fc2   = (const float*)d_in[15];
    const float* b_fc2   = (const float*)d_in[16];
    float* out = (float*)d_out;

    const int* src = ei;
    const int* dst = ei + NE;

    static float *p_xr1 = nullptr, *p_acc1 = nullptr, *p_xl = nullptr;
    if (!p_xr1) {
        cudaGetSymbolAddress((void**)&p_xr1, g_xr1);
        cudaGetSymbolAddress((void**)&p_acc1, g_acc1);
        cudaGetSymbolAddress((void**)&p_xl, g_xl);
    }

    const int GY = (NN + 127) / 128;   // 196

    zero_pool_kernel<<<16, 256>>>();

    // conv1 fused: [xr1 | acc1] = x @ [W1_rel | W1_root(+b1)]
    gemm128_kernel<<<dim3(1, GY), 256>>>(x, FEAT, FEAT, W1_rel, W1_root, 64,
                                         p_xr1, p_acc1, 64, NN, b1, 0);
    conv_edge_kernel<<<(NE * 16 + 255) / 256, 256>>>(src, dst);

    // GAT: xl = relu(h1) @ Wg   (N=256, contiguous)
    gemm128_kernel<<<dim3(2, GY), 256>>>(p_acc1, 64, 64, Wg, nullptr, 256,
                                         p_xl, nullptr, 256, NN, nullptr, 1);
    att_prep_kernel<<<(NN + 7) / 8, 256>>>(att_src, att_dst);
    edge_max_kernel<<<(NE + 255) / 256, 256>>>(src, dst);
    init_S_kernel<<<NN, 256>>>();
    gat_edge_kernel<<<(NE * 32 + 255) / 256, 256>>>(src, dst);
    h2_kernel<<<NN, 256>>>(bg);

    // conv5 fused: [xr5 | acc5] = h2 @ [W5_rel | W5_root(+b5)]
    gemm128_kernel<<<dim3(1, GY), 256>>>(p_xl, 256, 256, W5_rel, W5_root, 64,
                                         p_xr1, p_acc1, 64, NN, b5, 0);
    conv_edge_kernel<<<(NE * 16 + 255) / 256, 256>>>(src, dst);

    // pool + head
    pool_kernel<<<(NN + 63) / 64, 256>>>(batch);
    head_kernel<<<1, 256>>>(W_fc1, b_fc1, W_fc2, b_fc2, out);
}

// round 8
// speedup vs baseline: 1.0253x; 1.0112x over previous
#include <cuda_runtime.h>
#include <cstdint>

#define NN 25000
#define NE 400000
#define FEAT 128
#define HID 64
#define HEADS 4
#define NCLS 2
#define NGRAPH 64

// ---------------- scratch (device globals; no allocation) ----------------
__device__ alignas(16) float g_xr1 [NN * 64];          // rel-transformed (reused conv1/conv5)
__device__ alignas(16) float g_acc1[NN * 64];          // root-transform + bias, then +=agg
__device__ alignas(16) float g_xl  [(size_t)NN * 256]; // GAT transformed feats, later h2
__device__ alignas(16) float g_S   [(size_t)NN * 256]; // GAT unnormalized weighted sum
__device__ alignas(16) float g_as  [NN * 4];
__device__ alignas(16) float g_ad  [NN * 4];
__device__ alignas(16) float g_mf  [NN * 4];
__device__ alignas(16) float g_den [NN * 4];
__device__ alignas(16) unsigned g_menc[NN * 4];
__device__ alignas(16) float g_pool[NGRAPH * HID];

// ---------------- helpers ----------------
__device__ __forceinline__ float lrelu(float x) { return x > 0.f ? x : 0.2f * x; }

__device__ __forceinline__ unsigned fenc(float f) {
    unsigned u = __float_as_uint(f);
    return (u & 0x80000000u) ? ~u : (u | 0x80000000u);
}
__device__ __forceinline__ float fdec(unsigned u) {
    return __uint_as_float((u & 0x80000000u) ? (u & 0x7fffffffu) : ~u);
}

__device__ __forceinline__ void red4(float* p, float4 v) {
    asm volatile("red.global.add.v4.f32 [%0], {%1,%2,%3,%4};"
                 :: "l"(p), "f"(v.x), "f"(v.y), "f"(v.z), "f"(v.w) : "memory");
}

__device__ __forceinline__ unsigned long long packdup(float b) {
    unsigned long long r;
    asm("mov.b64 %0, {%1, %1};" : "=l"(r) : "f"(b));
    return r;
}
__device__ __forceinline__ void ffma2(unsigned long long& acc, unsigned long long a,
                                      unsigned long long b) {
    asm("fma.rn.f32x2 %0, %1, %2, %0;" : "+l"(acc) : "l"(a), "l"(b));
}
__device__ __forceinline__ unsigned long long add2(unsigned long long a, unsigned long long b) {
    unsigned long long r;
    asm("add.rn.f32x2 %0, %1, %2;" : "=l"(r) : "l"(a), "l"(b));
    return r;
}

// ============ 64x128-tile SGEMM, f32x2 pairs along N, double-buffered ============
// C = act(A[M,K]) @ B[K,*] (+bias on the C1 half)
// Split mode (B1 != null): B = [B0 | B1] each K x 64 (stride ldb); cols 0..63 -> C0,
//   cols 64..127 -> C1 (+bias1), both stride ldc.
// Contiguous mode (B1 == null): B0 is K x N (ldb); col block = blockIdx.x.
// 256 threads, per-thread 4 rows x 8 cols (4 f32x2 col-pairs). acc u64 == float2 of
// adjacent columns -> vectorized stores; B frags are native u64 pairs from SMEM.
__global__ __launch_bounds__(256, 3)
void gemm64_kernel(const float* __restrict__ A, int lda, int K,
                   const float* __restrict__ B0, const float* __restrict__ B1, int ldb,
                   float* __restrict__ C0, float* __restrict__ C1, int ldc,
                   int M, const float* __restrict__ bias1, int reluA)
{
    __shared__ alignas(16) float As[2][16][68];    // transposed A tile: As[buf][k][row]
    __shared__ alignas(16) float Bs[2][16][128];

    int tid = threadIdx.x;
    int row0 = blockIdx.y * 64;
    int col0 = blockIdx.x * 128;
    int ty = tid >> 4, tx = tid & 15;

    int ar = tid >> 2;                    // A tile row 0..63
    int ak = (tid & 3) * 4;               // A k-offset 0,4,8,12
    int bk = tid >> 4;                    // B tile k-row 0..15
    int bc = (tid & 15) * 8;              // B tile col 0..120

    int r = row0 + ar;
    bool aValid = (r < M);
    const float* aPtr = A + (size_t)(aValid ? r : 0) * lda + ak;
    const float* bPtr;
    if (B1) bPtr = (bc < 64) ? (B0 + (size_t)bk * ldb + bc)
                             : (B1 + (size_t)bk * ldb + bc - 64);
    else    bPtr = B0 + (size_t)bk * ldb + col0 + bc;
    size_t bStep = (size_t)16 * ldb;

    unsigned long long acc[4][4];
#pragma unroll
    for (int i = 0; i < 4; i++)
#pragma unroll
        for (int j = 0; j < 4; j++) acc[i][j] = 0ULL;

    float av[4], bv[8];
    // ---- prologue: tile 0 ----
    {
        float4 t0 = *(const float4*)aPtr;
        av[0]=t0.x; av[1]=t0.y; av[2]=t0.z; av[3]=t0.w;
        float4 u0 = *(const float4*)bPtr;
        float4 u1 = *(const float4*)(bPtr + 4);
        bv[0]=u0.x; bv[1]=u0.y; bv[2]=u0.z; bv[3]=u0.w;
        bv[4]=u1.x; bv[5]=u1.y; bv[6]=u1.z; bv[7]=u1.w;
    }
    if (!aValid) { av[0]=av[1]=av[2]=av[3]=0.f; }
    if (reluA) {
#pragma unroll
        for (int j = 0; j < 4; j++) av[j] = fmaxf(av[j], 0.f);
    }
#pragma unroll
    for (int j = 0; j < 4; j++) As[0][ak + j][ar] = av[j];
    *(float4*)&Bs[0][bk][bc]     = make_float4(bv[0], bv[1], bv[2], bv[3]);
    *(float4*)&Bs[0][bk][bc + 4] = make_float4(bv[4], bv[5], bv[6], bv[7]);
    __syncthreads();

    int T = K >> 4;
    for (int t = 0; t < T; t++) {
        int cur = t & 1, nxt = cur ^ 1;
        bool more = (t + 1 < T);
        if (more) {
            const float* ap = aPtr + (t + 1) * 16;
            float4 t0 = *(const float4*)ap;
            av[0]=t0.x; av[1]=t0.y; av[2]=t0.z; av[3]=t0.w;
            const float* bp = bPtr + (size_t)(t + 1) * bStep;
            float4 u0 = *(const float4*)bp;
            float4 u1 = *(const float4*)(bp + 4);
            bv[0]=u0.x; bv[1]=u0.y; bv[2]=u0.z; bv[3]=u0.w;
            bv[4]=u1.x; bv[5]=u1.y; bv[6]=u1.z; bv[7]=u1.w;
        }

#pragma unroll
        for (int k = 0; k < 16; k++) {
            // B: native u64 col-pairs, no packing
            ulonglong2 pb0 = *(const ulonglong2*)&Bs[cur][k][tx * 8];
            ulonglong2 pb1 = *(const ulonglong2*)&Bs[cur][k][tx * 8 + 4];
            unsigned long long b2[4] = {pb0.x, pb0.y, pb1.x, pb1.y};
            // A: 4 rows, duplicated into pairs (4 movs)
            float4 af = *(const float4*)&As[cur][k][ty * 4];
            unsigned long long a2[4];
            a2[0] = packdup(af.x); a2[1] = packdup(af.y);
            a2[2] = packdup(af.z); a2[3] = packdup(af.w);
#pragma unroll
            for (int rr = 0; rr < 4; rr++)
#pragma unroll
                for (int p = 0; p < 4; p++)
                    ffma2(acc[rr][p], a2[rr], b2[p]);
        }

        if (more) {
            if (!aValid) { av[0]=av[1]=av[2]=av[3]=0.f; }
            if (reluA) {
#pragma unroll
                for (int j = 0; j < 4; j++) av[j] = fmaxf(av[j], 0.f);
            }
#pragma unroll
            for (int j = 0; j < 4; j++) As[nxt][ak + j][ar] = av[j];
            *(float4*)&Bs[nxt][bk][bc]     = make_float4(bv[0], bv[1], bv[2], bv[3]);
            *(float4*)&Bs[nxt][bk][bc + 4] = make_float4(bv[4], bv[5], bv[6], bv[7]);
        }
        __syncthreads();
    }

    // ---- epilogue: acc[r][p] == float2 of cols (base+2p, base+2p+1) ----
    bool toC1 = (C1 != nullptr) && (tx >= 8);
    unsigned long long bp2[4] = {0ULL, 0ULL, 0ULL, 0ULL};
    if (toC1 && bias1) {
#pragma unroll
        for (int p = 0; p < 4; p++) {
            float2 bb = *(const float2*)(bias1 + (tx * 8 - 64) + 2 * p);
            unsigned long long t;
            asm("mov.b64 %0, {%1, %2};" : "=l"(t) : "f"(bb.x), "f"(bb.y));
            bp2[p] = t;
        }
    }
#pragma unroll
    for (int rr = 0; rr < 4; rr++) {
        int orow = row0 + ty * 4 + rr;
        if (orow >= M) continue;
        if (toC1) {
            float* cp = C1 + (size_t)orow * ldc + (tx * 8 - 64);
#pragma unroll
            for (int p = 0; p < 4; p++) {
                unsigned long long v = bias1 ? add2(acc[rr][p], bp2[p]) : acc[rr][p];
                *(float2*)(cp + 2 * p) = *(float2*)&v;
            }
        } else {
            float* cp = C0 + (size_t)orow * ldc + col0 + tx * 8;
#pragma unroll
            for (int p = 0; p < 4; p++)
                *(float2*)(cp + 2 * p) = *(float2*)&acc[rr][p];
        }
    }
}

// ---------------- conv edge scatter: g_acc1[dst] += g_xr1[src]  (64-dim) ----------------
__global__ void conv_edge_kernel(const int* __restrict__ src, const int* __restrict__ dst)
{
    int tid = blockIdx.x * 256 + threadIdx.x;
    int e = tid >> 4, t = tid & 15;
    if (e >= NE) return;
    int s = src[e], d = dst[e];
    float4 v = *(const float4*)(g_xr1 + (size_t)s * 64 + t * 4);
    red4(g_acc1 + (size_t)d * 64 + t * 4, v);
}

// ---------------- attention prep: a_s, a_d, init max with self-loop ----------------
__global__ void att_prep_kernel(const float* __restrict__ att_src, const float* __restrict__ att_dst)
{
    __shared__ float s_as[256], s_ad[256];
    int tid = threadIdx.x;
    if (tid < 256) { s_as[tid] = att_src[tid]; s_ad[tid] = att_dst[tid]; }
    __syncthreads();
    int warp = tid >> 5, lane = tid & 31;
    int n = blockIdx.x * 8 + warp;
    if (n >= NN) return;
    const float* xr = g_xl + (size_t)n * 256;
    float vs[4], vd[4];
#pragma unroll
    for (int h = 0; h < 4; h++) {
        float x0 = xr[h * 64 + lane], x1 = xr[h * 64 + lane + 32];
        float ps = x0 * s_as[h * 64 + lane] + x1 * s_as[h * 64 + lane + 32];
        float pd = x0 * s_ad[h * 64 + lane] + x1 * s_ad[h * 64 + lane + 32];
#pragma unroll
        for (int off = 16; off; off >>= 1) {
            ps += __shfl_down_sync(0xffffffffu, ps, off);
            pd += __shfl_down_sync(0xffffffffu, pd, off);
        }
        vs[h] = ps; vd[h] = pd;
    }
    if (lane == 0) {
#pragma unroll
        for (int h = 0; h < 4; h++) {
            g_as[n * 4 + h] = vs[h];
            g_ad[n * 4 + h] = vd[h];
            g_menc[n * 4 + h] = fenc(lrelu(vs[h] + vd[h]));   // self-loop seed
        }
    }
}

// ---------------- edge max pass ----------------
__global__ void edge_max_kernel(const int* __restrict__ src, const int* __restrict__ dst)
{
    int e = blockIdx.x * 256 + threadIdx.x;
    if (e >= NE) return;
    int s = src[e], d = dst[e];
    float4 a = *(const float4*)(g_as + s * 4);
    float4 b = *(const float4*)(g_ad + d * 4);
    float av[4] = {a.x, a.y, a.z, a.w}, bv[4] = {b.x, b.y, b.z, b.w};
#pragma unroll
    for (int h = 0; h < 4; h++)
        atomicMax(&g_menc[d * 4 + h], fenc(lrelu(av[h] + bv[h])));
}

// ---------------- init S/denom with self-loop contribution ----------------
__global__ void init_S_kernel()
{
    int idx = blockIdx.x * 256 + threadIdx.x;
    int n = idx >> 8, c = idx & 255, h = c >> 6;
    float mf = fdec(g_menc[n * 4 + h]);
    float es = lrelu(g_as[n * 4 + h] + g_ad[n * 4 + h]);
    float p = expf(es - mf);
    g_S[idx] = p * g_xl[idx];
    if (c < 4) {
        float mfh = fdec(g_menc[n * 4 + c]);
        g_mf[n * 4 + c] = mfh;
        float e2 = lrelu(g_as[n * 4 + c] + g_ad[n * 4 + c]);
        g_den[n * 4 + c] = expf(e2 - mfh);
    }
}

// ---------------- GAT edge pass 2: S[dst] += p*xl[src], denom[dst] += p ----------------
__global__ void gat_edge_kernel(const int* __restrict__ src, const int* __restrict__ dst)
{
    int gt = blockIdx.x * 256 + threadIdx.x;
    int e = gt >> 5, lane = gt & 31;
    if (e >= NE) return;
    int s = src[e], d = dst[e];
    float asv = (lane < 4) ? g_as[s * 4 + lane] : 0.f;
    float adv = (lane < 4) ? g_ad[d * 4 + lane] : 0.f;
    float mv  = (lane < 4) ? g_mf[d * 4 + lane] : 0.f;

    int h1 = lane >> 4;            // 0 or 1
    int h2 = 2 + (lane >> 4);      // 2 or 3
    int hd = lane & 3;             // head for denom-lane

    float e1 = lrelu(__shfl_sync(0xffffffffu, asv, h1) + __shfl_sync(0xffffffffu, adv, h1));
    float m1 = __shfl_sync(0xffffffffu, mv, h1);
    float e2 = lrelu(__shfl_sync(0xffffffffu, asv, h2) + __shfl_sync(0xffffffffu, adv, h2));
    float m2 = __shfl_sync(0xffffffffu, mv, h2);
    float ed = lrelu(__shfl_sync(0xffffffffu, asv, hd) + __shfl_sync(0xffffffffu, adv, hd));
    float md = __shfl_sync(0xffffffffu, mv, hd);

    float p1 = expf(e1 - m1);
    float p2 = expf(e2 - m2);
    float pd = expf(ed - md);

    const float* xr = g_xl + (size_t)s * 256;
    float* Sd = g_S + (size_t)d * 256;
    float4 v1 = *(const float4*)(xr + lane * 4);
    float4 v2 = *(const float4*)(xr + 128 + lane * 4);
    red4(Sd + lane * 4,       make_float4(p1 * v1.x, p1 * v1.y, p1 * v1.z, p1 * v1.w));
    red4(Sd + 128 + lane * 4, make_float4(p2 * v2.x, p2 * v2.y, p2 * v2.z, p2 * v2.w));
    if (lane < 4) atomicAdd(&g_den[d * 4 + lane], pd);
}

// ---------------- h2 = relu(S/denom + bg), written into g_xl ----------------
__global__ void h2_kernel(const float* __restrict__ bg)
{
    int idx = blockIdx.x * 256 + threadIdx.x;
    int n = idx >> 8, c = idx & 255, h = c >> 6;
    float v = g_S[idx] / g_den[n * 4 + h] + bg[c];
    g_xl[idx] = fmaxf(v, 0.f);
}

// ---------------- zero pool ----------------
__global__ void zero_pool_kernel()
{
    int t = blockIdx.x * 256 + threadIdx.x;
    if (t < NGRAPH * HID) g_pool[t] = 0.f;
}

// ---------------- pooling: g_pool[batch[n]] += relu(acc5[n])  (batch sorted) ----------------
__global__ void pool_kernel(const int* __restrict__ batch)
{
    int d = threadIdx.x & 63;
    int sub = threadIdx.x >> 6;
    int n0 = blockIdx.x * 64 + sub * 16;
    float sum = 0.f; int cur = -1;
#pragma unroll
    for (int i = 0; i < 16; i++) {
        int n = n0 + i;
        if (n >= NN) break;
        int b = batch[n];
        if (b != cur) {
            if (cur >= 0) atomicAdd(&g_pool[cur * 64 + d], sum);
            cur = b; sum = 0.f;
        }
        sum += fmaxf(g_acc1[(size_t)n * 64 + d], 0.f);
    }
    if (cur >= 0) atomicAdd(&g_pool[cur * 64 + d], sum);
}

// ---------------- head: relu(pool@Wfc1+b) @ Wfc2 + b -> sigmoid ----------------
__global__ void head_kernel(const float* __restrict__ Wfc1, const float* __restrict__ bfc1,
                            const float* __restrict__ Wfc2, const float* __restrict__ bfc2,
                            float* __restrict__ out)
{
    __shared__ float sg[64 * 64];
    __shared__ float sw[64 * 64];
    int t = threadIdx.x;
    for (int i = t; i < 4096; i += 256) { sg[i] = g_pool[i]; sw[i] = Wfc1[i]; }
    __syncthreads();
    float r[16];
#pragma unroll
    for (int i = 0; i < 16; i++) {
        int idx = t + 256 * i;
        int rr = idx >> 6, cc = idx & 63;
        float s = bfc1[cc];
#pragma unroll
        for (int k = 0; k < 64; k++) s += sg[rr * 64 + k] * sw[k * 64 + cc];
        r[i] = fmaxf(s, 0.f);
    }
    __syncthreads();
#pragma unroll
    for (int i = 0; i < 16; i++) sg[t + 256 * i] = r[i];
    __syncthreads();
    if (t < 128) {
        int rr = t >> 1, cc = t & 1;
        float s = bfc2[cc];
#pragma unroll
        for (int k = 0; k < 64; k++) s += sg[rr * 64 + k] * Wfc2[k * 2 + cc];
        out[t] = 1.f / (1.f + expf(-s));
    }
}

// ---------------- launch ----------------
extern "C" void kernel_launch(void* const* d_in, const int* in_sizes, int n_in,
                              void* d_out, int out_size)
{
    const float* x       = (const float*)d_in[0];
    const int*   ei      = (const int*)d_in[1];
    const int*   batch   = (const int*)d_in[2];
    const float* W1_rel  = (const float*)d_in[3];
    const float* b1      = (const float*)d_in[4];
    const float* W1_root = (const float*)d_in[5];
    const float* Wg      = (const float*)d_in[6];
    const float* att_src = (const float*)d_in[7];
    const float* att_dst = (const float*)d_in[8];
    const float* bg      = (const float*)d_in[9];
    const float* W5_rel  = (const float*)d_in[10];
    const float* b5      = (const float*)d_in[11];
    const float* W5_root = (const float*)d_in[12];
    const float* W_fc1   = (const float*)d_in[13];
    const float* b_fc1   = (const float*)d_in[14];
    const float* W_fc2   = (const float*)d_in[15];
    const float* b_fc2   = (const float*)d_in[16];
    float* out = (float*)d_out;

    const int* src = ei;
    const int* dst = ei + NE;

    static float *p_xr1 = nullptr, *p_acc1 = nullptr, *p_xl = nullptr;
    if (!p_xr1) {
        cudaGetSymbolAddress((void**)&p_xr1, g_xr1);
        cudaGetSymbolAddress((void**)&p_acc1, g_acc1);
        cudaGetSymbolAddress((void**)&p_xl, g_xl);
    }

    const int GY = (NN + 63) / 64;   // 391

    zero_pool_kernel<<<16, 256>>>();

    // conv1 fused: [xr1 | acc1] = x @ [W1_rel | W1_root(+b1)]
    gemm64_kernel<<<dim3(1, GY), 256>>>(x, FEAT, FEAT, W1_rel, W1_root, 64,
                                        p_xr1, p_acc1, 64, NN, b1, 0);
    conv_edge_kernel<<<(NE * 16 + 255) / 256, 256>>>(src, dst);

    // GAT: xl = relu(h1) @ Wg   (N=256, contiguous)
    gemm64_kernel<<<dim3(2, GY), 256>>>(p_acc1, 64, 64, Wg, nullptr, 256,
                                        p_xl, nullptr, 256, NN, nullptr, 1);
    att_prep_kernel<<<(NN + 7) / 8, 256>>>(att_src, att_dst);
    edge_max_kernel<<<(NE + 255) / 256, 256>>>(src, dst);
    init_S_kernel<<<NN, 256>>>();
    gat_edge_kernel<<<(NE * 32 + 255) / 256, 256>>>(src, dst);
    h2_kernel<<<NN, 256>>>(bg);

    // conv5 fused: [xr5 | acc5] = h2 @ [W5_rel | W5_root(+b5)]
    gemm64_kernel<<<dim3(1, GY), 256>>>(p_xl, 256, 256, W5_rel, W5_root, 64,
                                        p_xr1, p_acc1, 64, NN, b5, 0);
    conv_edge_kernel<<<(NE * 16 + 255) / 256, 256>>>(src, dst);

    // pool + head
    pool_kernel<<<(NN + 63) / 64, 256>>>(batch);
    head_kernel<<<1, 256>>>(W_fc1, b_fc1, W_fc2, b_fc2, out);
}

// round 9
// speedup vs baseline: 1.0432x; 1.0175x over previous
#include <cuda_runtime.h>
#include <cstdint>

#define NN 25000
#define NE 400000
#define FEAT 128
#define HID 64
#define HEADS 4
#define NCLS 2
#define NGRAPH 64

// ---------------- scratch (device globals; no allocation) ----------------
__device__ alignas(16) float g_xr1 [NN * 64];          // rel-transformed (reused conv1/conv5)
__device__ alignas(16) float g_acc1[NN * 64];          // root-transform + bias, then +=agg
__device__ alignas(16) float g_xl  [(size_t)NN * 256]; // GAT transformed feats, later h2
__device__ alignas(16) float g_S   [(size_t)NN * 256]; // GAT unnormalized weighted sum
__device__ alignas(16) float g_as  [NN * 4];
__device__ alignas(16) float g_ad  [NN * 4];
__device__ alignas(16) float g_mf  [NN * 4];
__device__ alignas(16) float g_den [NN * 4];
__device__ alignas(16) unsigned g_menc[NN * 4];
__device__ alignas(16) float g_pool[NGRAPH * HID];

// ---------------- helpers ----------------
__device__ __forceinline__ float lrelu(float x) { return x > 0.f ? x : 0.2f * x; }

__device__ __forceinline__ unsigned fenc(float f) {
    unsigned u = __float_as_uint(f);
    return (u & 0x80000000u) ? ~u : (u | 0x80000000u);
}
__device__ __forceinline__ float fdec(unsigned u) {
    return __uint_as_float((u & 0x80000000u) ? (u & 0x7fffffffu) : ~u);
}

__device__ __forceinline__ void red4(float* p, float4 v) {
    asm volatile("red.global.add.v4.f32 [%0], {%1,%2,%3,%4};"
                 :: "l"(p), "f"(v.x), "f"(v.y), "f"(v.z), "f"(v.w) : "memory");
}

__device__ __forceinline__ unsigned long long packdup(float b) {
    unsigned long long r;
    asm("mov.b64 %0, {%1, %1};" : "=l"(r) : "f"(b));
    return r;
}
__device__ __forceinline__ void ffma2(unsigned long long& acc, unsigned long long a,
                                      unsigned long long b) {
    asm("fma.rn.f32x2 %0, %1, %2, %0;" : "+l"(acc) : "l"(a), "l"(b));
}
__device__ __forceinline__ unsigned long long add2(unsigned long long a, unsigned long long b) {
    unsigned long long r;
    asm("add.rn.f32x2 %0, %1, %2;" : "=l"(r) : "l"(a), "l"(b));
    return r;
}

// ============ 64x128-tile SGEMM, f32x2 pairs along N ============
// Double-buffered SMEM tiles AND double-buffered register fragments:
// while k's 16 FFMA2 execute, k+1's LDS fragments are in flight.
// Split mode (B1 != null): B = [B0 | B1] each K x 64 (stride ldb); cols 0..63 -> C0,
//   cols 64..127 -> C1 (+bias1), both stride ldc.
// Contiguous mode (B1 == null): B0 is K x N (ldb); col block = blockIdx.x.
__global__ __launch_bounds__(256, 2)
void gemm64_kernel(const float* __restrict__ A, int lda, int K,
                   const float* __restrict__ B0, const float* __restrict__ B1, int ldb,
                   float* __restrict__ C0, float* __restrict__ C1, int ldc,
                   int M, const float* __restrict__ bias1, int reluA)
{
    __shared__ alignas(16) float As[2][16][68];    // transposed A tile: As[buf][k][row]
    __shared__ alignas(16) float Bs[2][16][128];

    int tid = threadIdx.x;
    int row0 = blockIdx.y * 64;
    int col0 = blockIdx.x * 128;
    int ty = tid >> 4, tx = tid & 15;

    int ar = tid >> 2;                    // A tile row 0..63
    int ak = (tid & 3) * 4;               // A k-offset 0,4,8,12
    int bk = tid >> 4;                    // B tile k-row 0..15
    int bc = (tid & 15) * 8;              // B tile col 0..120

    int r = row0 + ar;
    bool aValid = (r < M);
    const float* aPtr = A + (size_t)(aValid ? r : 0) * lda + ak;
    const float* bPtr;
    if (B1) bPtr = (bc < 64) ? (B0 + (size_t)bk * ldb + bc)
                             : (B1 + (size_t)bk * ldb + bc - 64);
    else    bPtr = B0 + (size_t)bk * ldb + col0 + bc;
    size_t bStep = (size_t)16 * ldb;

    unsigned long long acc[4][4];
#pragma unroll
    for (int i = 0; i < 4; i++)
#pragma unroll
        for (int j = 0; j < 4; j++) acc[i][j] = 0ULL;

    float av[4], bv[8];
    // ---- prologue: tile 0 ----
    {
        float4 t0 = *(const float4*)aPtr;
        av[0]=t0.x; av[1]=t0.y; av[2]=t0.z; av[3]=t0.w;
        float4 u0 = *(const float4*)bPtr;
        float4 u1 = *(const float4*)(bPtr + 4);
        bv[0]=u0.x; bv[1]=u0.y; bv[2]=u0.z; bv[3]=u0.w;
        bv[4]=u1.x; bv[5]=u1.y; bv[6]=u1.z; bv[7]=u1.w;
    }
    if (!aValid) { av[0]=av[1]=av[2]=av[3]=0.f; }
    if (reluA) {
#pragma unroll
        for (int j = 0; j < 4; j++) av[j] = fmaxf(av[j], 0.f);
    }
#pragma unroll
    for (int j = 0; j < 4; j++) As[0][ak + j][ar] = av[j];
    *(float4*)&Bs[0][bk][bc]     = make_float4(bv[0], bv[1], bv[2], bv[3]);
    *(float4*)&Bs[0][bk][bc + 4] = make_float4(bv[4], bv[5], bv[6], bv[7]);
    __syncthreads();

    int T = K >> 4;
    for (int t = 0; t < T; t++) {
        int cur = t & 1, nxt = cur ^ 1;
        bool more = (t + 1 < T);
        // ---- GMEM loads for next tile (covered by full 16-k compute) ----
        if (more) {
            const float* ap = aPtr + (t + 1) * 16;
            float4 t0 = *(const float4*)ap;
            av[0]=t0.x; av[1]=t0.y; av[2]=t0.z; av[3]=t0.w;
            const float* bp = bPtr + (size_t)(t + 1) * bStep;
            float4 u0 = *(const float4*)bp;
            float4 u1 = *(const float4*)(bp + 4);
            bv[0]=u0.x; bv[1]=u0.y; bv[2]=u0.z; bv[3]=u0.w;
            bv[4]=u1.x; bv[5]=u1.y; bv[6]=u1.z; bv[7]=u1.w;
        }

        // ---- k-loop with register fragment double-buffer ----
        ulonglong2 fb0 = *(const ulonglong2*)&Bs[cur][0][tx * 8];
        ulonglong2 fb1 = *(const ulonglong2*)&Bs[cur][0][tx * 8 + 4];
        float4     fa  = *(const float4*)&As[cur][0][ty * 4];
#pragma unroll
        for (int k = 0; k < 16; k++) {
            ulonglong2 nb0, nb1; float4 na;
            if (k < 15) {
                nb0 = *(const ulonglong2*)&Bs[cur][k + 1][tx * 8];
                nb1 = *(const ulonglong2*)&Bs[cur][k + 1][tx * 8 + 4];
                na  = *(const float4*)&As[cur][k + 1][ty * 4];
            }
            unsigned long long b2[4] = {fb0.x, fb0.y, fb1.x, fb1.y};
            unsigned long long a2[4];
            a2[0] = packdup(fa.x); a2[1] = packdup(fa.y);
            a2[2] = packdup(fa.z); a2[3] = packdup(fa.w);
#pragma unroll
            for (int rr = 0; rr < 4; rr++)
#pragma unroll
                for (int p = 0; p < 4; p++)
                    ffma2(acc[rr][p], a2[rr], b2[p]);
            if (k < 15) { fb0 = nb0; fb1 = nb1; fa = na; }
        }

        // ---- store next tile into the other buffer ----
        if (more) {
            if (!aValid) { av[0]=av[1]=av[2]=av[3]=0.f; }
            if (reluA) {
#pragma unroll
                for (int j = 0; j < 4; j++) av[j] = fmaxf(av[j], 0.f);
            }
#pragma unroll
            for (int j = 0; j < 4; j++) As[nxt][ak + j][ar] = av[j];
            *(float4*)&Bs[nxt][bk][bc]     = make_float4(bv[0], bv[1], bv[2], bv[3]);
            *(float4*)&Bs[nxt][bk][bc + 4] = make_float4(bv[4], bv[5], bv[6], bv[7]);
        }
        __syncthreads();
    }

    // ---- epilogue: acc[r][p] == float2 of cols (base+2p, base+2p+1) ----
    bool toC1 = (C1 != nullptr) && (tx >= 8);
    unsigned long long bp2[4] = {0ULL, 0ULL, 0ULL, 0ULL};
    if (toC1 && bias1) {
#pragma unroll
        for (int p = 0; p < 4; p++) {
            float2 bb = *(const float2*)(bias1 + (tx * 8 - 64) + 2 * p);
            unsigned long long t;
            asm("mov.b64 %0, {%1, %2};" : "=l"(t) : "f"(bb.x), "f"(bb.y));
            bp2[p] = t;
        }
    }
#pragma unroll
    for (int rr = 0; rr < 4; rr++) {
        int orow = row0 + ty * 4 + rr;
        if (orow >= M) continue;
        if (toC1) {
            float* cp = C1 + (size_t)orow * ldc + (tx * 8 - 64);
#pragma unroll
            for (int p = 0; p < 4; p++) {
                unsigned long long v = bias1 ? add2(acc[rr][p], bp2[p]) : acc[rr][p];
                *(float2*)(cp + 2 * p) = *(float2*)&v;
            }
        } else {
            float* cp = C0 + (size_t)orow * ldc + col0 + tx * 8;
#pragma unroll
            for (int p = 0; p < 4; p++)
                *(float2*)(cp + 2 * p) = *(float2*)&acc[rr][p];
        }
    }
}

// ---------------- conv edge scatter: g_acc1[dst] += g_xr1[src]  (64-dim) ----------------
__global__ void conv_edge_kernel(const int* __restrict__ src, const int* __restrict__ dst)
{
    int tid = blockIdx.x * 256 + threadIdx.x;
    int e = tid >> 4, t = tid & 15;
    if (e >= NE) return;
    int s = src[e], d = dst[e];
    float4 v = *(const float4*)(g_xr1 + (size_t)s * 64 + t * 4);
    red4(g_acc1 + (size_t)d * 64 + t * 4, v);
}

// ---------------- attention prep: a_s, a_d, init max with self-loop ----------------
__global__ void att_prep_kernel(const float* __restrict__ att_src, const float* __restrict__ att_dst)
{
    __shared__ float s_as[256], s_ad[256];
    int tid = threadIdx.x;
    if (tid < 256) { s_as[tid] = att_src[tid]; s_ad[tid] = att_dst[tid]; }
    __syncthreads();
    int warp = tid >> 5, lane = tid & 31;
    int n = blockIdx.x * 8 + warp;
    if (n >= NN) return;
    const float* xr = g_xl + (size_t)n * 256;
    float vs[4], vd[4];
#pragma unroll
    for (int h = 0; h < 4; h++) {
        float x0 = xr[h * 64 + lane], x1 = xr[h * 64 + lane + 32];
        float ps = x0 * s_as[h * 64 + lane] + x1 * s_as[h * 64 + lane + 32];
        float pd = x0 * s_ad[h * 64 + lane] + x1 * s_ad[h * 64 + lane + 32];
#pragma unroll
        for (int off = 16; off; off >>= 1) {
            ps += __shfl_down_sync(0xffffffffu, ps, off);
            pd += __shfl_down_sync(0xffffffffu, pd, off);
        }
        vs[h] = ps; vd[h] = pd;
    }
    if (lane == 0) {
#pragma unroll
        for (int h = 0; h < 4; h++) {
            g_as[n * 4 + h] = vs[h];
            g_ad[n * 4 + h] = vd[h];
            g_menc[n * 4 + h] = fenc(lrelu(vs[h] + vd[h]));   // self-loop seed
        }
    }
}

// ---------------- edge max pass ----------------
__global__ void edge_max_kernel(const int* __restrict__ src, const int* __restrict__ dst)
{
    int e = blockIdx.x * 256 + threadIdx.x;
    if (e >= NE) return;
    int s = src[e], d = dst[e];
    float4 a = *(const float4*)(g_as + s * 4);
    float4 b = *(const float4*)(g_ad + d * 4);
    float av[4] = {a.x, a.y, a.z, a.w}, bv[4] = {b.x, b.y, b.z, b.w};
#pragma unroll
    for (int h = 0; h < 4; h++)
        atomicMax(&g_menc[d * 4 + h], fenc(lrelu(av[h] + bv[h])));
}

// ---------------- init S/denom with self-loop contribution ----------------
__global__ void init_S_kernel()
{
    int idx = blockIdx.x * 256 + threadIdx.x;
    int n = idx >> 8, c = idx & 255, h = c >> 6;
    float mf = fdec(g_menc[n * 4 + h]);
    float es = lrelu(g_as[n * 4 + h] + g_ad[n * 4 + h]);
    float p = expf(es - mf);
    g_S[idx] = p * g_xl[idx];
    if (c < 4) {
        float mfh = fdec(g_menc[n * 4 + c]);
        g_mf[n * 4 + c] = mfh;
        float e2 = lrelu(g_as[n * 4 + c] + g_ad[n * 4 + c]);
        g_den[n * 4 + c] = expf(e2 - mfh);
    }
}

// ---------------- GAT edge pass 2: S[dst] += p*xl[src], denom[dst] += p ----------------
__global__ void gat_edge_kernel(const int* __restrict__ src, const int* __restrict__ dst)
{
    int gt = blockIdx.x * 256 + threadIdx.x;
    int e = gt >> 5, lane = gt & 31;
    if (e >= NE) return;
    int s = src[e], d = dst[e];
    float asv = (lane < 4) ? g_as[s * 4 + lane] : 0.f;
    float adv = (lane < 4) ? g_ad[d * 4 + lane] : 0.f;
    float mv  = (lane < 4) ? g_mf[d * 4 + lane] : 0.f;

    int h1 = lane >> 4;            // 0 or 1
    int h2 = 2 + (lane >> 4);      // 2 or 3
    int hd = lane & 3;             // head for denom-lane

    float e1 = lrelu(__shfl_sync(0xffffffffu, asv, h1) + __shfl_sync(0xffffffffu, adv, h1));
    float m1 = __shfl_sync(0xffffffffu, mv, h1);
    float e2 = lrelu(__shfl_sync(0xffffffffu, asv, h2) + __shfl_sync(0xffffffffu, adv, h2));
    float m2 = __shfl_sync(0xffffffffu, mv, h2);
    float ed = lrelu(__shfl_sync(0xffffffffu, asv, hd) + __shfl_sync(0xffffffffu, adv, hd));
    float md = __shfl_sync(0xffffffffu, mv, hd);

    float p1 = expf(e1 - m1);
    float p2 = expf(e2 - m2);
    float pd = expf(ed - md);

    const float* xr = g_xl + (size_t)s * 256;
    float* Sd = g_S + (size_t)d * 256;
    float4 v1 = *(const float4*)(xr + lane * 4);
    float4 v2 = *(const float4*)(xr + 128 + lane * 4);
    red4(Sd + lane * 4,       make_float4(p1 * v1.x, p1 * v1.y, p1 * v1.z, p1 * v1.w));
    red4(Sd + 128 + lane * 4, make_float4(p2 * v2.x, p2 * v2.y, p2 * v2.z, p2 * v2.w));
    if (lane < 4) atomicAdd(&g_den[d * 4 + lane], pd);
}

// ---------------- h2 = relu(S/denom + bg), written into g_xl ----------------
__global__ void h2_kernel(const float* __restrict__ bg)
{
    int idx = blockIdx.x * 256 + threadIdx.x;
    int n = idx >> 8, c = idx & 255, h = c >> 6;
    float v = g_S[idx] / g_den[n * 4 + h] + bg[c];
    g_xl[idx] = fmaxf(v, 0.f);
}

// ---------------- zero pool ----------------
__global__ void zero_pool_kernel()
{
    int t = blockIdx.x * 256 + threadIdx.x;
    if (t < NGRAPH * HID) g_pool[t] = 0.f;
}

// ---------------- pooling: g_pool[batch[n]] += relu(acc5[n])  (batch sorted) ----------------
__global__ void pool_kernel(const int* __restrict__ batch)
{
    int d = threadIdx.x & 63;
    int sub = threadIdx.x >> 6;
    int n0 = blockIdx.x * 64 + sub * 16;
    float sum = 0.f; int cur = -1;
#pragma unroll
    for (int i = 0; i < 16; i++) {
        int n = n0 + i;
        if (n >= NN) break;
        int b = batch[n];
        if (b != cur) {
            if (cur >= 0) atomicAdd(&g_pool[cur * 64 + d], sum);
            cur = b; sum = 0.f;
        }
        sum += fmaxf(g_acc1[(size_t)n * 64 + d], 0.f);
    }
    if (cur >= 0) atomicAdd(&g_pool[cur * 64 + d], sum);
}

// ---------------- head: relu(pool@Wfc1+b) @ Wfc2 + b -> sigmoid ----------------
__global__ void head_kernel(const float* __restrict__ Wfc1, const float* __restrict__ bfc1,
                            const float* __restrict__ Wfc2, const float* __restrict__ bfc2,
                            float* __restrict__ out)
{
    __shared__ float sg[64 * 64];
    __shared__ float sw[64 * 64];
    int t = threadIdx.x;
    for (int i = t; i < 4096; i += 256) { sg[i] = g_pool[i]; sw[i] = Wfc1[i]; }
    __syncthreads();
    float r[16];
#pragma unroll
    for (int i = 0; i < 16; i++) {
        int idx = t + 256 * i;
        int rr = idx >> 6, cc = idx & 63;
        float s = bfc1[cc];
#pragma unroll
        for (int k = 0; k < 64; k++) s += sg[rr * 64 + k] * sw[k * 64 + cc];
        r[i] = fmaxf(s, 0.f);
    }
    __syncthreads();
#pragma unroll
    for (int i = 0; i < 16; i++) sg[t + 256 * i] = r[i];
    __syncthreads();
    if (t < 128) {
        int rr = t >> 1, cc = t & 1;
        float s = bfc2[cc];
#pragma unroll
        for (int k = 0; k < 64; k++) s += sg[rr * 64 + k] * Wfc2[k * 2 + cc];
        out[t] = 1.f / (1.f + expf(-s));
    }
}

// ---------------- launch ----------------
extern "C" void kernel_launch(void* const* d_in, const int* in_sizes, int n_in,
                              void* d_out, int out_size)
{
    const float* x       = (const float*)d_in[0];
    const int*   ei      = (const int*)d_in[1];
    const int*   batch   = (const int*)d_in[2];
    const float* W1_rel  = (const float*)d_in[3];
    const float* b1      = (const float*)d_in[4];
    const float* W1_root = (const float*)d_in[5];
    const float* Wg      = (const float*)d_in[6];
    const float* att_src = (const float*)d_in[7];
    const float* att_dst = (const float*)d_in[8];
    const float* bg      = (const float*)d_in[9];
    const float* W5_rel  = (const float*)d_in[10];
    const float* b5      = (const float*)d_in[11];
    const float* W5_root = (const float*)d_in[12];
    const float* W_fc1   = (const float*)d_in[13];
    const float* b_fc1   = (const float*)d_in[14];
    const float* W_fc2   = (const float*)d_in[15];
    const float* b_fc2   = (const float*)d_in[16];
    float* out = (float*)d_out;

    const int* src = ei;
    const int* dst = ei + NE;

    static float *p_xr1 = nullptr, *p_acc1 = nullptr, *p_xl = nullptr;
    if (!p_xr1) {
        cudaGetSymbolAddress((void**)&p_xr1, g_xr1);
        cudaGetSymbolAddress((void**)&p_acc1, g_acc1);
        cudaGetSymbolAddress((void**)&p_xl, g_xl);
    }

    const int GY = (NN + 63) / 64;   // 391

    zero_pool_kernel<<<16, 256>>>();

    // conv1 fused: [xr1 | acc1] = x @ [W1_rel | W1_root(+b1)]
    gemm64_kernel<<<dim3(1, GY), 256>>>(x, FEAT, FEAT, W1_rel, W1_root, 64,
                                        p_xr1, p_acc1, 64, NN, b1, 0);
    conv_edge_kernel<<<(NE * 16 + 255) / 256, 256>>>(src, dst);

    // GAT: xl = relu(h1) @ Wg   (N=256, contiguous)
    gemm64_kernel<<<dim3(2, GY), 256>>>(p_acc1, 64, 64, Wg, nullptr, 256,
                                        p_xl, nullptr, 256, NN, nullptr, 1);
    att_prep_kernel<<<(NN + 7) / 8, 256>>>(att_src, att_dst);
    edge_max_kernel<<<(NE + 255) / 256, 256>>>(src, dst);
    init_S_kernel<<<NN, 256>>>();
    gat_edge_kernel<<<(NE * 32 + 255) / 256, 256>>>(src, dst);
    h2_kernel<<<NN, 256>>>(bg);

    // conv5 fused: [xr5 | acc5] = h2 @ [W5_rel | W5_root(+b5)]
    gemm64_kernel<<<dim3(1, GY), 256>>>(p_xl, 256, 256, W5_rel, W5_root, 64,
                                        p_xr1, p_acc1, 64, NN, b5, 0);
    conv_edge_kernel<<<(NE * 16 + 255) / 256, 256>>>(src, dst);

    // pool + head
    pool_kernel<<<(NN + 63) / 64, 256>>>(batch);
    head_kernel<<<1, 256>>>(W_fc1, b_fc1, W_fc2, b_fc2, out);
}

// round 12
// speedup vs baseline: 1.1859x; 1.1367x over previous
#include <cuda_runtime.h>
#include <cstdint>

#define NN 25000
#define NE 400000
#define FEAT 128
#define HID 64
#define HEADS 4
#define NCLS 2
#define NGRAPH 64
#define SCAN_T 1024
#define SCAN_CH 25   // ceil(NN/SCAN_T)

// ---------------- scratch (device globals; no allocation) ----------------
__device__ alignas(16) float g_xr1 [NN * 64];          // rel-transformed (conv1/conv5)
__device__ alignas(16) float g_acc1[NN * 64];          // root-transform + bias, then +=agg
__device__ alignas(16) float g_xl  [(size_t)NN * 256]; // GAT transformed feats (xl)
__device__ alignas(16) float g_S   [(size_t)NN * 256]; // h2 output (relu'd GAT result)
__device__ alignas(16) float g_as  [NN * 4];
__device__ alignas(16) float g_ad  [NN * 4];
__device__ alignas(16) float g_pool[NGRAPH * HID];
// CSR by destination
__device__ int g_deg[NN];
__device__ int g_off[NN + 1];
__device__ int g_cur[NN];
__device__ int g_esrc[NE];

// ---------------- helpers ----------------
__device__ __forceinline__ float lrelu(float x) { return x > 0.f ? x : 0.2f * x; }

__device__ __forceinline__ unsigned long long packdup(float b) {
    unsigned long long r;
    asm("mov.b64 %0, {%1, %1};" : "=l"(r) : "f"(b));
    return r;
}
__device__ __forceinline__ void ffma2(unsigned long long& acc, unsigned long long a,
                                      unsigned long long b) {
    asm("fma.rn.f32x2 %0, %1, %2, %0;" : "+l"(acc) : "l"(a), "l"(b));
}
__device__ __forceinline__ unsigned long long add2(unsigned long long a, unsigned long long b) {
    unsigned long long r;
    asm("add.rn.f32x2 %0, %1, %2;" : "=l"(r) : "l"(a), "l"(b));
    return r;
}

// ============ 64x128-tile SGEMM, f32x2 pairs along N (round-9 best) ============
__global__ __launch_bounds__(256, 2)
void gemm64_kernel(const float* __restrict__ A, int lda, int K,
                   const float* __restrict__ B0, const float* __restrict__ B1, int ldb,
                   float* __restrict__ C0, float* __restrict__ C1, int ldc,
                   int M, const float* __restrict__ bias1, int reluA)
{
    __shared__ alignas(16) float As[2][16][68];
    __shared__ alignas(16) float Bs[2][16][128];

    int tid = threadIdx.x;
    int row0 = blockIdx.y * 64;
    int col0 = blockIdx.x * 128;
    int ty = tid >> 4, tx = tid & 15;

    int ar = tid >> 2;
    int ak = (tid & 3) * 4;
    int bk = tid >> 4;
    int bc = (tid & 15) * 8;

    int r = row0 + ar;
    bool aValid = (r < M);
    const float* aPtr = A + (size_t)(aValid ? r : 0) * lda + ak;
    const float* bPtr;
    if (B1) bPtr = (bc < 64) ? (B0 + (size_t)bk * ldb + bc)
                             : (B1 + (size_t)bk * ldb + bc - 64);
    else    bPtr = B0 + (size_t)bk * ldb + col0 + bc;
    size_t bStep = (size_t)16 * ldb;

    unsigned long long acc[4][4];
#pragma unroll
    for (int i = 0; i < 4; i++)
#pragma unroll
        for (int j = 0; j < 4; j++) acc[i][j] = 0ULL;

    float av[4], bv[8];
    {
        float4 t0 = *(const float4*)aPtr;
        av[0]=t0.x; av[1]=t0.y; av[2]=t0.z; av[3]=t0.w;
        float4 u0 = *(const float4*)bPtr;
        float4 u1 = *(const float4*)(bPtr + 4);
        bv[0]=u0.x; bv[1]=u0.y; bv[2]=u0.z; bv[3]=u0.w;
        bv[4]=u1.x; bv[5]=u1.y; bv[6]=u1.z; bv[7]=u1.w;
    }
    if (!aValid) { av[0]=av[1]=av[2]=av[3]=0.f; }
    if (reluA) {
#pragma unroll
        for (int j = 0; j < 4; j++) av[j] = fmaxf(av[j], 0.f);
    }
#pragma unroll
    for (int j = 0; j < 4; j++) As[0][ak + j][ar] = av[j];
    *(float4*)&Bs[0][bk][bc]     = make_float4(bv[0], bv[1], bv[2], bv[3]);
    *(float4*)&Bs[0][bk][bc + 4] = make_float4(bv[4], bv[5], bv[6], bv[7]);
    __syncthreads();

    int T = K >> 4;
    for (int t = 0; t < T; t++) {
        int cur = t & 1, nxt = cur ^ 1;
        bool more = (t + 1 < T);
        if (more) {
            const float* ap = aPtr + (t + 1) * 16;
            float4 t0 = *(const float4*)ap;
            av[0]=t0.x; av[1]=t0.y; av[2]=t0.z; av[3]=t0.w;
            const float* bp = bPtr + (size_t)(t + 1) * bStep;
            float4 u0 = *(const float4*)bp;
            float4 u1 = *(const float4*)(bp + 4);
            bv[0]=u0.x; bv[1]=u0.y; bv[2]=u0.z; bv[3]=u0.w;
            bv[4]=u1.x; bv[5]=u1.y; bv[6]=u1.z; bv[7]=u1.w;
        }

        ulonglong2 fb0 = *(const ulonglong2*)&Bs[cur][0][tx * 8];
        ulonglong2 fb1 = *(const ulonglong2*)&Bs[cur][0][tx * 8 + 4];
        float4     fa  = *(const float4*)&As[cur][0][ty * 4];
#pragma unroll
        for (int k = 0; k < 16; k++) {
            ulonglong2 nb0, nb1; float4 na;
            if (k < 15) {
                nb0 = *(const ulonglong2*)&Bs[cur][k + 1][tx * 8];
                nb1 = *(const ulonglong2*)&Bs[cur][k + 1][tx * 8 + 4];
                na  = *(const float4*)&As[cur][k + 1][ty * 4];
            }
            unsigned long long b2[4] = {fb0.x, fb0.y, fb1.x, fb1.y};
            unsigned long long a2[4];
            a2[0] = packdup(fa.x); a2[1] = packdup(fa.y);
            a2[2] = packdup(fa.z); a2[3] = packdup(fa.w);
#pragma unroll
            for (int rr = 0; rr < 4; rr++)
#pragma unroll
                for (int p = 0; p < 4; p++)
                    ffma2(acc[rr][p], a2[rr], b2[p]);
            if (k < 15) { fb0 = nb0; fb1 = nb1; fa = na; }
        }

        if (more) {
            if (!aValid) { av[0]=av[1]=av[2]=av[3]=0.f; }
            if (reluA) {
#pragma unroll
                for (int j = 0; j < 4; j++) av[j] = fmaxf(av[j], 0.f);
            }
#pragma unroll
            for (int j = 0; j < 4; j++) As[nxt][ak + j][ar] = av[j];
            *(float4*)&Bs[nxt][bk][bc]     = make_float4(bv[0], bv[1], bv[2], bv[3]);
            *(float4*)&Bs[nxt][bk][bc + 4] = make_float4(bv[4], bv[5], bv[6], bv[7]);
        }
        __syncthreads();
    }

    bool toC1 = (C1 != nullptr) && (tx >= 8);
    unsigned long long bp2[4] = {0ULL, 0ULL, 0ULL, 0ULL};
    if (toC1 && bias1) {
#pragma unroll
        for (int p = 0; p < 4; p++) {
            float2 bb = *(const float2*)(bias1 + (tx * 8 - 64) + 2 * p);
            unsigned long long t;
            asm("mov.b64 %0, {%1, %2};" : "=l"(t) : "f"(bb.x), "f"(bb.y));
            bp2[p] = t;
        }
    }
#pragma unroll
    for (int rr = 0; rr < 4; rr++) {
        int orow = row0 + ty * 4 + rr;
        if (orow >= M) continue;
        if (toC1) {
            float* cp = C1 + (size_t)orow * ldc + (tx * 8 - 64);
#pragma unroll
            for (int p = 0; p < 4; p++) {
                unsigned long long v = bias1 ? add2(acc[rr][p], bp2[p]) : acc[rr][p];
                *(float2*)(cp + 2 * p) = *(float2*)&v;
            }
        } else {
            float* cp = C0 + (size_t)orow * ldc + col0 + tx * 8;
#pragma unroll
            for (int p = 0; p < 4; p++)
                *(float2*)(cp + 2 * p) = *(float2*)&acc[rr][p];
        }
    }
}

// ================= CSR build =================
__global__ void init_kernel()
{
    int t = blockIdx.x * 256 + threadIdx.x;
    if (t < NN) g_deg[t] = 0;
    if (t < NGRAPH * HID) g_pool[t] = 0.f;
}

__global__ void csr_count_kernel(const int* __restrict__ dst)
{
    int e = blockIdx.x * 256 + threadIdx.x;
    if (e < NE) atomicAdd(&g_deg[dst[e]], 1);
}

__global__ void csr_scan_kernel()
{
    __shared__ int ssum[SCAN_T];
    int t = threadIdx.x;
    int base = t * SCAN_CH;
    int total = 0;
#pragma unroll
    for (int i = 0; i < SCAN_CH; i++) {
        int idx = base + i;
        if (idx < NN) total += g_deg[idx];
    }
    ssum[t] = total;
    __syncthreads();
    for (int d = 1; d < SCAN_T; d <<= 1) {
        int add = (t >= d) ? ssum[t - d] : 0;
        __syncthreads();
        ssum[t] += add;
        __syncthreads();
    }
    int run = ssum[t] - total;   // exclusive prefix
#pragma unroll
    for (int i = 0; i < SCAN_CH; i++) {
        int idx = base + i;
        if (idx < NN) {
            g_off[idx] = run;
            g_cur[idx] = run;
            run += g_deg[idx];
        }
    }
    if (t == SCAN_T - 1) g_off[NN] = run;
}

__global__ void csr_scatter_kernel(const int* __restrict__ src, const int* __restrict__ dst)
{
    int e = blockIdx.x * 256 + threadIdx.x;
    if (e >= NE) return;
    int d = dst[e];
    int pos = atomicAdd(&g_cur[d], 1);
    g_esrc[pos] = src[e];
}

// ---------------- conv gather: g_acc1[d] += sum_{s->d} g_xr1[s]  (64-dim, no atomics) ----
__global__ __launch_bounds__(256)
void conv_gather_kernel()
{
    int half = threadIdx.x >> 4;            // 0..15
    int lane16 = threadIdx.x & 15;
    int d = blockIdx.x * 16 + half;
    if (d >= NN) return;
    int beg = g_off[d], end = g_off[d + 1];
    float ax = 0.f, ay = 0.f, az = 0.f, aw = 0.f;
    for (int i = beg; i < end; i++) {
        int s = g_esrc[i];                  // broadcast load within half-warp
        float4 v = *(const float4*)(g_xr1 + (size_t)s * 64 + lane16 * 4);
        ax += v.x; ay += v.y; az += v.z; aw += v.w;
    }
    float* p = g_acc1 + (size_t)d * 64 + lane16 * 4;
    float4 o = *(float4*)p;
    o.x += ax; o.y += ay; o.z += az; o.w += aw;
    *(float4*)p = o;
}

// ---------------- attention prep: a_s, a_d per node ----------------
__global__ void att_prep_kernel(const float* __restrict__ att_src, const float* __restrict__ att_dst)
{
    __shared__ float s_as[256], s_ad[256];
    int tid = threadIdx.x;
    if (tid < 256) { s_as[tid] = att_src[tid]; s_ad[tid] = att_dst[tid]; }
    __syncthreads();
    int warp = tid >> 5, lane = tid & 31;
    int n = blockIdx.x * 8 + warp;
    if (n >= NN) return;
    const float* xr = g_xl + (size_t)n * 256;
    float vs[4], vd[4];
#pragma unroll
    for (int h = 0; h < 4; h++) {
        float x0 = xr[h * 64 + lane], x1 = xr[h * 64 + lane + 32];
        float ps = x0 * s_as[h * 64 + lane] + x1 * s_as[h * 64 + lane + 32];
        float pd = x0 * s_ad[h * 64 + lane] + x1 * s_ad[h * 64 + lane + 32];
#pragma unroll
        for (int off = 16; off; off >>= 1) {
            ps += __shfl_down_sync(0xffffffffu, ps, off);
            pd += __shfl_down_sync(0xffffffffu, pd, off);
        }
        vs[h] = ps; vd[h] = pd;
    }
    if (lane == 0) {
#pragma unroll
        for (int h = 0; h < 4; h++) {
            g_as[n * 4 + h] = vs[h];
            g_ad[n * 4 + h] = vd[h];
        }
    }
}

// ---------------- fused GAT per node: max + softmax + aggregate + bias + relu ----------
// one warp per node; h2 written to g_S (xl stays intact while other nodes read it)
__global__ __launch_bounds__(256)
void gat_node_kernel(const float* __restrict__ bg)
{
    int warp = threadIdx.x >> 5, lane = threadIdx.x & 31;
    int d = blockIdx.x * 8 + warp;
    if (d >= NN) return;
    int beg = g_off[d], end = g_off[d + 1];

    float4 ad4 = *(const float4*)(g_ad + d * 4);
    float4 as_d = *(const float4*)(g_as + d * 4);
    float4 sl;   // self-loop logits
    sl.x = lrelu(as_d.x + ad4.x); sl.y = lrelu(as_d.y + ad4.y);
    sl.z = lrelu(as_d.z + ad4.z); sl.w = lrelu(as_d.w + ad4.w);

    // ---- pass 1: per-head max over in-edges (+self) ----
    float4 m4 = sl;
    for (int i = beg + lane; i < end; i += 32) {
        int s = g_esrc[i];
        float4 a4 = *(const float4*)(g_as + s * 4);
        m4.x = fmaxf(m4.x, lrelu(a4.x + ad4.x));
        m4.y = fmaxf(m4.y, lrelu(a4.y + ad4.y));
        m4.z = fmaxf(m4.z, lrelu(a4.z + ad4.z));
        m4.w = fmaxf(m4.w, lrelu(a4.w + ad4.w));
    }
#pragma unroll
    for (int off = 16; off; off >>= 1) {
        m4.x = fmaxf(m4.x, __shfl_xor_sync(0xffffffffu, m4.x, off));
        m4.y = fmaxf(m4.y, __shfl_xor_sync(0xffffffffu, m4.y, off));
        m4.z = fmaxf(m4.z, __shfl_xor_sync(0xffffffffu, m4.z, off));
        m4.w = fmaxf(m4.w, __shfl_xor_sync(0xffffffffu, m4.w, off));
    }

    // ---- pass 2: accumulate p*xl; lane covers cols lane*4 (heads 0/1) and 128+lane*4 (heads 2/3)
    int hsel = lane >> 4;    // 0 -> heads 0/2 ; 1 -> heads 1/3
    float4 acc0, acc1, den;
    {
        float px = expf(sl.x - m4.x), py = expf(sl.y - m4.y);
        float pz = expf(sl.z - m4.z), pw = expf(sl.w - m4.w);
        den = make_float4(px, py, pz, pw);
        const float* xp = g_xl + (size_t)d * 256;
        float4 v0 = *(const float4*)(xp + lane * 4);
        float4 v1 = *(const float4*)(xp + 128 + lane * 4);
        float q0 = hsel ? py : px;
        float q1 = hsel ? pw : pz;
        acc0 = make_float4(q0 * v0.x, q0 * v0.y, q0 * v0.z, q0 * v0.w);
        acc1 = make_float4(q1 * v1.x, q1 * v1.y, q1 * v1.z, q1 * v1.w);
    }

    for (int i0 = beg; i0 < end; i0 += 32) {
        int i = i0 + lane;
        int s = 0; float px = 0.f, py = 0.f, pz = 0.f, pw = 0.f;
        if (i < end) {
            s = g_esrc[i];
            float4 a4 = *(const float4*)(g_as + s * 4);
            px = expf(lrelu(a4.x + ad4.x) - m4.x);
            py = expf(lrelu(a4.y + ad4.y) - m4.y);
            pz = expf(lrelu(a4.z + ad4.z) - m4.z);
            pw = expf(lrelu(a4.w + ad4.w) - m4.w);
        }
        int cnt = end - i0; if (cnt > 32) cnt = 32;
        for (int j = 0; j < cnt; j++) {
            int   sj = __shfl_sync(0xffffffffu, s, j);
            float qx = __shfl_sync(0xffffffffu, px, j);
            float qy = __shfl_sync(0xffffffffu, py, j);
            float qz = __shfl_sync(0xffffffffu, pz, j);
            float qw = __shfl_sync(0xffffffffu, pw, j);
            den.x += qx; den.y += qy; den.z += qz; den.w += qw;
            const float* xp = g_xl + (size_t)sj * 256;
            float4 v0 = *(const float4*)(xp + lane * 4);
            float4 v1 = *(const float4*)(xp + 128 + lane * 4);
            float q0 = hsel ? qy : qx;
            float q1 = hsel ? qw : qz;
            acc0.x += q0 * v0.x; acc0.y += q0 * v0.y; acc0.z += q0 * v0.z; acc0.w += q0 * v0.w;
            acc1.x += q1 * v1.x; acc1.y += q1 * v1.y; acc1.z += q1 * v1.z; acc1.w += q1 * v1.w;
        }
    }

    float d0 = hsel ? den.y : den.x;
    float d1 = hsel ? den.w : den.z;
    float4 b0 = *(const float4*)(bg + lane * 4);
    float4 b1 = *(const float4*)(bg + 128 + lane * 4);
    float inv0 = 1.f / d0, inv1 = 1.f / d1;
    float4 o0, o1;
    o0.x = fmaxf(acc0.x * inv0 + b0.x, 0.f); o0.y = fmaxf(acc0.y * inv0 + b0.y, 0.f);
    o0.z = fmaxf(acc0.z * inv0 + b0.z, 0.f); o0.w = fmaxf(acc0.w * inv0 + b0.w, 0.f);
    o1.x = fmaxf(acc1.x * inv1 + b1.x, 0.f); o1.y = fmaxf(acc1.y * inv1 + b1.y, 0.f);
    o1.z = fmaxf(acc1.z * inv1 + b1.z, 0.f); o1.w = fmaxf(acc1.w * inv1 + b1.w, 0.f);
    float* op = g_S + (size_t)d * 256;
    *(float4*)(op + lane * 4) = o0;
    *(float4*)(op + 128 + lane * 4) = o1;
}

// ---------------- pooling: g_pool[batch[n]] += relu(acc5[n])  (batch sorted) ----------------
__global__ void pool_kernel(const int* __restrict__ batch)
{
    int d = threadIdx.x & 63;
    int sub = threadIdx.x >> 6;
    int n0 = blockIdx.x * 64 + sub * 16;
    float sum = 0.f; int cur = -1;
#pragma unroll
    for (int i = 0; i < 16; i++) {
        int n = n0 + i;
        if (n >= NN) break;
        int b = batch[n];
        if (b != cur) {
            if (cur >= 0) atomicAdd(&g_pool[cur * 64 + d], sum);
            cur = b; sum = 0.f;
        }
        sum += fmaxf(g_acc1[(size_t)n * 64 + d], 0.f);
    }
    if (cur >= 0) atomicAdd(&g_pool[cur * 64 + d], sum);
}

// ---------------- head ----------------
__global__ void head_kernel(const float* __restrict__ Wfc1, const float* __restrict__ bfc1,
                            const float* __restrict__ Wfc2, const float* __restrict__ bfc2,
                            float* __restrict__ out)
{
    __shared__ float sg[64 * 64];
    __shared__ float sw[64 * 64];
    int t = threadIdx.x;
    for (int i = t; i < 4096; i += 256) { sg[i] = g_pool[i]; sw[i] = Wfc1[i]; }
    __syncthreads();
    float r[16];
#pragma unroll
    for (int i = 0; i < 16; i++) {
        int idx = t + 256 * i;
        int rr = idx >> 6, cc = idx & 63;
        float s = bfc1[cc];
#pragma unroll
        for (int k = 0; k < 64; k++) s += sg[rr * 64 + k] * sw[k * 64 + cc];
        r[i] = fmaxf(s, 0.f);
    }
    __syncthreads();
#pragma unroll
    for (int i = 0; i < 16; i++) sg[t + 256 * i] = r[i];
    __syncthreads();
    if (t < 128) {
        int rr = t >> 1, cc = t & 1;
        float s = bfc2[cc];
#pragma unroll
        for (int k = 0; k < 64; k++) s += sg[rr * 64 + k] * Wfc2[k * 2 + cc];
        out[t] = 1.f / (1.f + expf(-s));
    }
}

// ---------------- launch ----------------
extern "C" void kernel_launch(void* const* d_in, const int* in_sizes, int n_in,
                              void* d_out, int out_size)
{
    const float* x       = (const float*)d_in[0];
    const int*   ei      = (const int*)d_in[1];
    const int*   batch   = (const int*)d_in[2];
    const float* W1_rel  = (const float*)d_in[3];
    const float* b1      = (const float*)d_in[4];
    const float* W1_root = (const float*)d_in[5];
    const float* Wg      = (const float*)d_in[6];
    const float* att_src = (const float*)d_in[7];
    const float* att_dst = (const float*)d_in[8];
    const float* bg      = (const float*)d_in[9];
    const float* W5_rel  = (const float*)d_in[10];
    const float* b5      = (const float*)d_in[11];
    const float* W5_root = (const float*)d_in[12];
    const float* W_fc1   = (const float*)d_in[13];
    const float* b_fc1   = (const float*)d_in[14];
    const float* W_fc2   = (const float*)d_in[15];
    const float* b_fc2   = (const float*)d_in[16];
    float* out = (float*)d_out;

    const int* src = ei;
    const int* dst = ei + NE;

    static float *p_xr1 = nullptr, *p_acc1 = nullptr, *p_xl = nullptr, *p_S = nullptr;
    if (!p_xr1) {
        cudaGetSymbolAddress((void**)&p_xr1, g_xr1);
        cudaGetSymbolAddress((void**)&p_acc1, g_acc1);
        cudaGetSymbolAddress((void**)&p_xl, g_xl);
        cudaGetSymbolAddress((void**)&p_S, g_S);
    }

    const int GY = (NN + 63) / 64;   // 391

    // CSR build
    init_kernel<<<(NN + 255) / 256, 256>>>();
    csr_count_kernel<<<(NE + 255) / 256, 256>>>(dst);
    csr_scan_kernel<<<1, SCAN_T>>>();
    csr_scatter_kernel<<<(NE + 255) / 256, 256>>>(src, dst);

    // conv1 fused: [xr1 | acc1] = x @ [W1_rel | W1_root(+b1)]
    gemm64_kernel<<<dim3(1, GY), 256>>>(x, FEAT, FEAT, W1_rel, W1_root, 64,
                                        p_xr1, p_acc1, 64, NN, b1, 0);
    conv_gather_kernel<<<(NN + 15) / 16, 256>>>();

    // GAT: xl = relu(h1) @ Wg   (N=256, contiguous)
    gemm64_kernel<<<dim3(2, GY), 256>>>(p_acc1, 64, 64, Wg, nullptr, 256,
                                        p_xl, nullptr, 256, NN, nullptr, 1);
    att_prep_kernel<<<(NN + 7) / 8, 256>>>(att_src, att_dst);
    gat_node_kernel<<<(NN + 7) / 8, 256>>>(bg);

    // conv5 fused: [xr5 | acc5] = h2 @ [W5_rel | W5_root(+b5)]  (h2 lives in g_S)
    gemm64_kernel<<<dim3(1, GY), 256>>>(p_S, 256, 256, W5_rel, W5_root, 64,
                                        p_xr1, p_acc1, 64, NN, b5, 0);
    conv_gather_kernel<<<(NN + 15) / 16, 256>>>();

    // pool + head
    pool_kernel<<<(NN + 63) / 64, 256>>>(batch);
    head_kernel<<<1, 256>>>(W_fc1, b_fc1, W_fc2, b_fc2, out);
}

// round 13
// speedup vs baseline: 1.2702x; 1.0712x over previous
#include <cuda_runtime.h>
#include <cstdint>

#define NN 25000
#define NE 400000
#define FEAT 128
#define HID 64
#define HEADS 4
#define NCLS 2
#define NGRAPH 64
#define SCAN_T 1024
#define SCAN_CH 25   // ceil(NN/SCAN_T)

// ---------------- scratch (device globals; no allocation) ----------------
__device__ alignas(16) float g_xr1 [NN * 64];          // rel-transformed (conv1/conv5)
__device__ alignas(16) float g_acc1[NN * 64];          // root-transform + bias, then +=agg
__device__ alignas(16) float g_xl  [(size_t)NN * 256]; // GAT transformed feats (xl)
__device__ alignas(16) float g_S   [(size_t)NN * 256]; // h2 output (relu'd GAT result)
__device__ alignas(16) float g_as  [NN * 4];
__device__ alignas(16) float g_ad  [NN * 4];
__device__ alignas(16) float g_pool[NGRAPH * HID];
// CSR by destination
__device__ int g_deg[NN];
__device__ int g_off[NN + 1];
__device__ int g_cur[NN];
__device__ int g_esrc[NE];

// ---------------- helpers ----------------
__device__ __forceinline__ float lrelu(float x) { return x > 0.f ? x : 0.2f * x; }

__device__ __forceinline__ unsigned long long packdup(float b) {
    unsigned long long r;
    asm("mov.b64 %0, {%1, %1};" : "=l"(r) : "f"(b));
    return r;
}
__device__ __forceinline__ void ffma2(unsigned long long& acc, unsigned long long a,
                                      unsigned long long b) {
    asm("fma.rn.f32x2 %0, %1, %2, %0;" : "+l"(acc) : "l"(a), "l"(b));
}
__device__ __forceinline__ unsigned long long add2(unsigned long long a, unsigned long long b) {
    unsigned long long r;
    asm("add.rn.f32x2 %0, %1, %2;" : "=l"(r) : "l"(a), "l"(b));
    return r;
}

// ============ 128x128-tile SGEMM, f32x2 pairs along N, crossbar-balanced ============
// Per thread: 8 rows x 8 cols (4 f32x2 col-pairs) -> 64 B LDS per 64 FMAs (1 B/FMA).
// SMEM double-buffered + register fragment prefetch inside the k-loop.
// Split mode (B1 != null): B = [B0 | B1] each K x 64 (stride ldb); cols 0..63 -> C0,
//   cols 64..127 -> C1 (+bias1), both stride ldc.
// Contiguous mode (B1 == null): B0 is K x N (ldb); col block = blockIdx.x.
__global__ __launch_bounds__(256, 2)
void gemm128_kernel(const float* __restrict__ A, int lda, int K,
                    const float* __restrict__ B0, const float* __restrict__ B1, int ldb,
                    float* __restrict__ C0, float* __restrict__ C1, int ldc,
                    int M, const float* __restrict__ bias1, int reluA)
{
    __shared__ alignas(16) float As[2][16][132];   // transposed A tile: As[buf][k][row]
    __shared__ alignas(16) float Bs[2][16][128];

    int tid = threadIdx.x;
    int row0 = blockIdx.y * 128;
    int col0 = blockIdx.x * 128;
    int ty = tid >> 4, tx = tid & 15;

    int ar = tid >> 1;                    // A tile row 0..127
    int ak = (tid & 1) * 8;               // A k-offset 0 or 8
    int bk = tid >> 4;                    // B tile k-row 0..15
    int bc = (tid & 15) * 8;              // B tile col 0..120

    int r = row0 + ar;
    bool aValid = (r < M);
    const float* aPtr = A + (size_t)(aValid ? r : 0) * lda + ak;
    const float* bPtr;
    if (B1) bPtr = (bc < 64) ? (B0 + (size_t)bk * ldb + bc)
                             : (B1 + (size_t)bk * ldb + bc - 64);
    else    bPtr = B0 + (size_t)bk * ldb + col0 + bc;
    size_t bStep = (size_t)16 * ldb;

    unsigned long long acc[8][4];
#pragma unroll
    for (int i = 0; i < 8; i++)
#pragma unroll
        for (int j = 0; j < 4; j++) acc[i][j] = 0ULL;

    float av[8], bv[8];
    // ---- prologue: tile 0 ----
    {
        float4 t0 = *(const float4*)aPtr;
        float4 t1 = *(const float4*)(aPtr + 4);
        av[0]=t0.x; av[1]=t0.y; av[2]=t0.z; av[3]=t0.w;
        av[4]=t1.x; av[5]=t1.y; av[6]=t1.z; av[7]=t1.w;
        float4 u0 = *(const float4*)bPtr;
        float4 u1 = *(const float4*)(bPtr + 4);
        bv[0]=u0.x; bv[1]=u0.y; bv[2]=u0.z; bv[3]=u0.w;
        bv[4]=u1.x; bv[5]=u1.y; bv[6]=u1.z; bv[7]=u1.w;
    }
    if (!aValid) {
#pragma unroll
        for (int j = 0; j < 8; j++) av[j] = 0.f;
    }
    if (reluA) {
#pragma unroll
        for (int j = 0; j < 8; j++) av[j] = fmaxf(av[j], 0.f);
    }
#pragma unroll
    for (int j = 0; j < 8; j++) As[0][ak + j][ar] = av[j];
    *(float4*)&Bs[0][bk][bc]     = make_float4(bv[0], bv[1], bv[2], bv[3]);
    *(float4*)&Bs[0][bk][bc + 4] = make_float4(bv[4], bv[5], bv[6], bv[7]);
    __syncthreads();

    int T = K >> 4;
    for (int t = 0; t < T; t++) {
        int cur = t & 1, nxt = cur ^ 1;
        bool more = (t + 1 < T);
        // ---- GMEM loads for next tile ----
        if (more) {
            const float* ap = aPtr + (t + 1) * 16;
            float4 t0 = *(const float4*)ap;
            float4 t1 = *(const float4*)(ap + 4);
            av[0]=t0.x; av[1]=t0.y; av[2]=t0.z; av[3]=t0.w;
            av[4]=t1.x; av[5]=t1.y; av[6]=t1.z; av[7]=t1.w;
            const float* bp = bPtr + (size_t)(t + 1) * bStep;
            float4 u0 = *(const float4*)bp;
            float4 u1 = *(const float4*)(bp + 4);
            bv[0]=u0.x; bv[1]=u0.y; bv[2]=u0.z; bv[3]=u0.w;
            bv[4]=u1.x; bv[5]=u1.y; bv[6]=u1.z; bv[7]=u1.w;
        }

        // ---- k-loop with register fragment prefetch ----
        ulonglong2 fb0 = *(const ulonglong2*)&Bs[cur][0][tx * 8];
        ulonglong2 fb1 = *(const ulonglong2*)&Bs[cur][0][tx * 8 + 4];
        float4     fa0 = *(const float4*)&As[cur][0][ty * 8];
        float4     fa1 = *(const float4*)&As[cur][0][ty * 8 + 4];
#pragma unroll
        for (int k = 0; k < 16; k++) {
            ulonglong2 nb0, nb1; float4 na0, na1;
            if (k < 15) {
                nb0 = *(const ulonglong2*)&Bs[cur][k + 1][tx * 8];
                nb1 = *(const ulonglong2*)&Bs[cur][k + 1][tx * 8 + 4];
                na0 = *(const float4*)&As[cur][k + 1][ty * 8];
                na1 = *(const float4*)&As[cur][k + 1][ty * 8 + 4];
            }
            unsigned long long b2[4] = {fb0.x, fb0.y, fb1.x, fb1.y};
            unsigned long long a2[8];
            a2[0] = packdup(fa0.x); a2[1] = packdup(fa0.y);
            a2[2] = packdup(fa0.z); a2[3] = packdup(fa0.w);
            a2[4] = packdup(fa1.x); a2[5] = packdup(fa1.y);
            a2[6] = packdup(fa1.z); a2[7] = packdup(fa1.w);
#pragma unroll
            for (int rr = 0; rr < 8; rr++)
#pragma unroll
                for (int p = 0; p < 4; p++)
                    ffma2(acc[rr][p], a2[rr], b2[p]);
            if (k < 15) { fb0 = nb0; fb1 = nb1; fa0 = na0; fa1 = na1; }
        }

        // ---- store next tile ----
        if (more) {
            if (!aValid) {
#pragma unroll
                for (int j = 0; j < 8; j++) av[j] = 0.f;
            }
            if (reluA) {
#pragma unroll
                for (int j = 0; j < 8; j++) av[j] = fmaxf(av[j], 0.f);
            }
#pragma unroll
            for (int j = 0; j < 8; j++) As[nxt][ak + j][ar] = av[j];
            *(float4*)&Bs[nxt][bk][bc]     = make_float4(bv[0], bv[1], bv[2], bv[3]);
            *(float4*)&Bs[nxt][bk][bc + 4] = make_float4(bv[4], bv[5], bv[6], bv[7]);
        }
        __syncthreads();
    }

    // ---- epilogue: acc[r][p] == float2 of cols (base+2p, base+2p+1) ----
    bool toC1 = (C1 != nullptr) && (tx >= 8);
    unsigned long long bp2[4] = {0ULL, 0ULL, 0ULL, 0ULL};
    if (toC1 && bias1) {
#pragma unroll
        for (int p = 0; p < 4; p++) {
            float2 bb = *(const float2*)(bias1 + (tx * 8 - 64) + 2 * p);
            unsigned long long t;
            asm("mov.b64 %0, {%1, %2};" : "=l"(t) : "f"(bb.x), "f"(bb.y));
            bp2[p] = t;
        }
    }
#pragma unroll
    for (int rr = 0; rr < 8; rr++) {
        int orow = row0 + ty * 8 + rr;
        if (orow >= M) continue;
        if (toC1) {
            float* cp = C1 + (size_t)orow * ldc + (tx * 8 - 64);
#pragma unroll
            for (int p = 0; p < 4; p++) {
                unsigned long long v = bias1 ? add2(acc[rr][p], bp2[p]) : acc[rr][p];
                *(float2*)(cp + 2 * p) = *(float2*)&v;
            }
        } else {
            float* cp = C0 + (size_t)orow * ldc + col0 + tx * 8;
#pragma unroll
            for (int p = 0; p < 4; p++)
                *(float2*)(cp + 2 * p) = *(float2*)&acc[rr][p];
        }
    }
}

// ================= CSR build =================
__global__ void init_kernel()
{
    int t = blockIdx.x * 256 + threadIdx.x;
    if (t < NN) g_deg[t] = 0;
    if (t < NGRAPH * HID) g_pool[t] = 0.f;
}

__global__ void csr_count_kernel(const int* __restrict__ dst)
{
    int e = blockIdx.x * 256 + threadIdx.x;
    if (e < NE) atomicAdd(&g_deg[dst[e]], 1);
}

__global__ void csr_scan_kernel()
{
    __shared__ int ssum[SCAN_T];
    int t = threadIdx.x;
    int base = t * SCAN_CH;
    int total = 0;
#pragma unroll
    for (int i = 0; i < SCAN_CH; i++) {
        int idx = base + i;
        if (idx < NN) total += g_deg[idx];
    }
    ssum[t] = total;
    __syncthreads();
    for (int d = 1; d < SCAN_T; d <<= 1) {
        int add = (t >= d) ? ssum[t - d] : 0;
        __syncthreads();
        ssum[t] += add;
        __syncthreads();
    }
    int run = ssum[t] - total;   // exclusive prefix
#pragma unroll
    for (int i = 0; i < SCAN_CH; i++) {
        int idx = base + i;
        if (idx < NN) {
            g_off[idx] = run;
            g_cur[idx] = run;
            run += g_deg[idx];
        }
    }
    if (t == SCAN_T - 1) g_off[NN] = run;
}

__global__ void csr_scatter_kernel(const int* __restrict__ src, const int* __restrict__ dst)
{
    int e = blockIdx.x * 256 + threadIdx.x;
    if (e >= NE) return;
    int d = dst[e];
    int pos = atomicAdd(&g_cur[d], 1);
    g_esrc[pos] = src[e];
}

// ---------------- conv gather: g_acc1[d] += sum_{s->d} g_xr1[s]  (64-dim, no atomics) ----
__global__ __launch_bounds__(256)
void conv_gather_kernel()
{
    int half = threadIdx.x >> 4;            // 0..15
    int lane16 = threadIdx.x & 15;
    int d = blockIdx.x * 16 + half;
    if (d >= NN) return;
    int beg = g_off[d], end = g_off[d + 1];
    float ax = 0.f, ay = 0.f, az = 0.f, aw = 0.f;
    for (int i = beg; i < end; i++) {
        int s = g_esrc[i];                  // broadcast load within half-warp
        float4 v = *(const float4*)(g_xr1 + (size_t)s * 64 + lane16 * 4);
        ax += v.x; ay += v.y; az += v.z; aw += v.w;
    }
    float* p = g_acc1 + (size_t)d * 64 + lane16 * 4;
    float4 o = *(float4*)p;
    o.x += ax; o.y += ay; o.z += az; o.w += aw;
    *(float4*)p = o;
}

// ---------------- attention prep: a_s, a_d per node ----------------
__global__ void att_prep_kernel(const float* __restrict__ att_src, const float* __restrict__ att_dst)
{
    __shared__ float s_as[256], s_ad[256];
    int tid = threadIdx.x;
    if (tid < 256) { s_as[tid] = att_src[tid]; s_ad[tid] = att_dst[tid]; }
    __syncthreads();
    int warp = tid >> 5, lane = tid & 31;
    int n = blockIdx.x * 8 + warp;
    if (n >= NN) return;
    const float* xr = g_xl + (size_t)n * 256;
    float vs[4], vd[4];
#pragma unroll
    for (int h = 0; h < 4; h++) {
        float x0 = xr[h * 64 + lane], x1 = xr[h * 64 + lane + 32];
        float ps = x0 * s_as[h * 64 + lane] + x1 * s_as[h * 64 + lane + 32];
        float pd = x0 * s_ad[h * 64 + lane] + x1 * s_ad[h * 64 + lane + 32];
#pragma unroll
        for (int off = 16; off; off >>= 1) {
            ps += __shfl_down_sync(0xffffffffu, ps, off);
            pd += __shfl_down_sync(0xffffffffu, pd, off);
        }
        vs[h] = ps; vd[h] = pd;
    }
    if (lane == 0) {
#pragma unroll
        for (int h = 0; h < 4; h++) {
            g_as[n * 4 + h] = vs[h];
            g_ad[n * 4 + h] = vd[h];
        }
    }
}

// ---------------- fused GAT per node: max + softmax + aggregate + bias + relu ----------
__global__ __launch_bounds__(256)
void gat_node_kernel(const float* __restrict__ bg)
{
    int warp = threadIdx.x >> 5, lane = threadIdx.x & 31;
    int d = blockIdx.x * 8 + warp;
    if (d >= NN) return;
    int beg = g_off[d], end = g_off[d + 1];

    float4 ad4 = *(const float4*)(g_ad + d * 4);
    float4 as_d = *(const float4*)(g_as + d * 4);
    float4 sl;   // self-loop logits
    sl.x = lrelu(as_d.x + ad4.x); sl.y = lrelu(as_d.y + ad4.y);
    sl.z = lrelu(as_d.z + ad4.z); sl.w = lrelu(as_d.w + ad4.w);

    // ---- pass 1: per-head max over in-edges (+self) ----
    float4 m4 = sl;
    for (int i = beg + lane; i < end; i += 32) {
        int s = g_esrc[i];
        float4 a4 = *(const float4*)(g_as + s * 4);
        m4.x = fmaxf(m4.x, lrelu(a4.x + ad4.x));
        m4.y = fmaxf(m4.y, lrelu(a4.y + ad4.y));
        m4.z = fmaxf(m4.z, lrelu(a4.z + ad4.z));
        m4.w = fmaxf(m4.w, lrelu(a4.w + ad4.w));
    }
#pragma unroll
    for (int off = 16; off; off >>= 1) {
        m4.x = fmaxf(m4.x, __shfl_xor_sync(0xffffffffu, m4.x, off));
        m4.y = fmaxf(m4.y, __shfl_xor_sync(0xffffffffu, m4.y, off));
        m4.z = fmaxf(m4.z, __shfl_xor_sync(0xffffffffu, m4.z, off));
        m4.w = fmaxf(m4.w, __shfl_xor_sync(0xffffffffu, m4.w, off));
    }

    // ---- pass 2: accumulate p*xl ----
    int hsel = lane >> 4;    // 0 -> heads 0/2 ; 1 -> heads 1/3
    float4 acc0, acc1, den;
    {
        float px = expf(sl.x - m4.x), py = expf(sl.y - m4.y);
        float pz = expf(sl.z - m4.z), pw = expf(sl.w - m4.w);
        den = make_float4(px, py, pz, pw);
        const float* xp = g_xl + (size_t)d * 256;
        float4 v0 = *(const float4*)(xp + lane * 4);
        float4 v1 = *(const float4*)(xp + 128 + lane * 4);
        float q0 = hsel ? py : px;
        float q1 = hsel ? pw : pz;
        acc0 = make_float4(q0 * v0.x, q0 * v0.y, q0 * v0.z, q0 * v0.w);
        acc1 = make_float4(q1 * v1.x, q1 * v1.y, q1 * v1.z, q1 * v1.w);
    }

    for (int i0 = beg; i0 < end; i0 += 32) {
        int i = i0 + lane;
        int s = 0; float px = 0.f, py = 0.f, pz = 0.f, pw = 0.f;
        if (i < end) {
            s = g_esrc[i];
            float4 a4 = *(const float4*)(g_as + s * 4);
            px = expf(lrelu(a4.x + ad4.x) - m4.x);
            py = expf(lrelu(a4.y + ad4.y) - m4.y);
            pz = expf(lrelu(a4.z + ad4.z) - m4.z);
            pw = expf(lrelu(a4.w + ad4.w) - m4.w);
        }
        int cnt = end - i0; if (cnt > 32) cnt = 32;
        for (int j = 0; j < cnt; j++) {
            int   sj = __shfl_sync(0xffffffffu, s, j);
            float qx = __shfl_sync(0xffffffffu, px, j);
            float qy = __shfl_sync(0xffffffffu, py, j);
            float qz = __shfl_sync(0xffffffffu, pz, j);
            float qw = __shfl_sync(0xffffffffu, pw, j);
            den.x += qx; den.y += qy; den.z += qz; den.w += qw;
            const float* xp = g_xl + (size_t)sj * 256;
            float4 v0 = *(const float4*)(xp + lane * 4);
            float4 v1 = *(const float4*)(xp + 128 + lane * 4);
            float q0 = hsel ? qy : qx;
            float q1 = hsel ? qw : qz;
            acc0.x += q0 * v0.x; acc0.y += q0 * v0.y; acc0.z += q0 * v0.z; acc0.w += q0 * v0.w;
            acc1.x += q1 * v1.x; acc1.y += q1 * v1.y; acc1.z += q1 * v1.z; acc1.w += q1 * v1.w;
        }
    }

    float d0 = hsel ? den.y : den.x;
    float d1 = hsel ? den.w : den.z;
    float4 b0 = *(const float4*)(bg + lane * 4);
    float4 b1 = *(const float4*)(bg + 128 + lane * 4);
    float inv0 = 1.f / d0, inv1 = 1.f / d1;
    float4 o0, o1;
    o0.x = fmaxf(acc0.x * inv0 + b0.x, 0.f); o0.y = fmaxf(acc0.y * inv0 + b0.y, 0.f);
    o0.z = fmaxf(acc0.z * inv0 + b0.z, 0.f); o0.w = fmaxf(acc0.w * inv0 + b0.w, 0.f);
    o1.x = fmaxf(acc1.x * inv1 + b1.x, 0.f); o1.y = fmaxf(acc1.y * inv1 + b1.y, 0.f);
    o1.z = fmaxf(acc1.z * inv1 + b1.z, 0.f); o1.w = fmaxf(acc1.w * inv1 + b1.w, 0.f);
    float* op = g_S + (size_t)d * 256;
    *(float4*)(op + lane * 4) = o0;
    *(float4*)(op + 128 + lane * 4) = o1;
}

// ---------------- pooling: g_pool[batch[n]] += relu(acc5[n])  (batch sorted) ----------------
__global__ void pool_kernel(const int* __restrict__ batch)
{
    int d = threadIdx.x & 63;
    int sub = threadIdx.x >> 6;
    int n0 = blockIdx.x * 64 + sub * 16;
    float sum = 0.f; int cur = -1;
#pragma unroll
    for (int i = 0; i < 16; i++) {
        int n = n0 + i;
        if (n >= NN) break;
        int b = batch[n];
        if (b != cur) {
            if (cur >= 0) atomicAdd(&g_pool[cur * 64 + d], sum);
            cur = b; sum = 0.f;
        }
        sum += fmaxf(g_acc1[(size_t)n * 64 + d], 0.f);
    }
    if (cur >= 0) atomicAdd(&g_pool[cur * 64 + d], sum);
}

// ---------------- head ----------------
__global__ void head_kernel(const float* __restrict__ Wfc1, const float* __restrict__ bfc1,
                            const float* __restrict__ Wfc2, const float* __restrict__ bfc2,
                            float* __restrict__ out)
{
    __shared__ float sg[64 * 64];
    __shared__ float sw[64 * 64];
    int t = threadIdx.x;
    for (int i = t; i < 4096; i += 256) { sg[i] = g_pool[i]; sw[i] = Wfc1[i]; }
    __syncthreads();
    float r[16];
#pragma unroll
    for (int i = 0; i < 16; i++) {
        int idx = t + 256 * i;
        int rr = idx >> 6, cc = idx & 63;
        float s = bfc1[cc];
#pragma unroll
        for (int k = 0; k < 64; k++) s += sg[rr * 64 + k] * sw[k * 64 + cc];
        r[i] = fmaxf(s, 0.f);
    }
    __syncthreads();
#pragma unroll
    for (int i = 0; i < 16; i++) sg[t + 256 * i] = r[i];
    __syncthreads();
    if (t < 128) {
        int rr = t >> 1, cc = t & 1;
        float s = bfc2[cc];
#pragma unroll
        for (int k = 0; k < 64; k++) s += sg[rr * 64 + k] * Wfc2[k * 2 + cc];
        out[t] = 1.f / (1.f + expf(-s));
    }
}

// ---------------- launch ----------------
extern "C" void kernel_launch(void* const* d_in, const int* in_sizes, int n_in,
                              void* d_out, int out_size)
{
    const float* x       = (const float*)d_in[0];
    const int*   ei      = (const int*)d_in[1];
    const int*   batch   = (const int*)d_in[2];
    const float* W1_rel  = (const float*)d_in[3];
    const float* b1      = (const float*)d_in[4];
    const float* W1_root = (const float*)d_in[5];
    const float* Wg      = (const float*)d_in[6];
    const float* att_src = (const float*)d_in[7];
    const float* att_dst = (const float*)d_in[8];
    const float* bg      = (const float*)d_in[9];
    const float* W5_rel  = (const float*)d_in[10];
    const float* b5      = (const float*)d_in[11];
    const float* W5_root = (const float*)d_in[12];
    const float* W_fc1   = (const float*)d_in[13];
    const float* b_fc1   = (const float*)d_in[14];
    const float* W_fc2   = (const float*)d_in[15];
    const float* b_fc2   = (const float*)d_in[16];
    float* out = (float*)d_out;

    const int* src = ei;
    const int* dst = ei + NE;

    static float *p_xr1 = nullptr, *p_acc1 = nullptr, *p_xl = nullptr, *p_S = nullptr;
    if (!p_xr1) {
        cudaGetSymbolAddress((void**)&p_xr1, g_xr1);
        cudaGetSymbolAddress((void**)&p_acc1, g_acc1);
        cudaGetSymbolAddress((void**)&p_xl, g_xl);
        cudaGetSymbolAddress((void**)&p_S, g_S);
    }

    const int GY = (NN + 127) / 128;   // 196

    // CSR build
    init_kernel<<<(NN + 255) / 256, 256>>>();
    csr_count_kernel<<<(NE + 255) / 256, 256>>>(dst);
    csr_scan_kernel<<<1, SCAN_T>>>();
    csr_scatter_kernel<<<(NE + 255) / 256, 256>>>(src, dst);

    // conv1 fused: [xr1 | acc1] = x @ [W1_rel | W1_root(+b1)]
    gemm128_kernel<<<dim3(1, GY), 256>>>(x, FEAT, FEAT, W1_rel, W1_root, 64,
                                         p_xr1, p_acc1, 64, NN, b1, 0);
    conv_gather_kernel<<<(NN + 15) / 16, 256>>>();

    // GAT: xl = relu(h1) @ Wg   (N=256, contiguous)
    gemm128_kernel<<<dim3(2, GY), 256>>>(p_acc1, 64, 64, Wg, nullptr, 256,
                                         p_xl, nullptr, 256, NN, nullptr, 1);
    att_prep_kernel<<<(NN + 7) / 8, 256>>>(att_src, att_dst);
    gat_node_kernel<<<(NN + 7) / 8, 256>>>(bg);

    // conv5 fused: [xr5 | acc5] = h2 @ [W5_rel | W5_root(+b5)]  (h2 lives in g_S)
    gemm128_kernel<<<dim3(1, GY), 256>>>(p_S, 256, 256, W5_rel, W5_root, 64,
                                         p_xr1, p_acc1, 64, NN, b5, 0);
    conv_gather_kernel<<<(NN + 15) / 16, 256>>>();

    // pool + head
    pool_kernel<<<(NN + 63) / 64, 256>>>(batch);
    head_kernel<<<1, 256>>>(W_fc1, b_fc1, W_fc2, b_fc2, out);
}

// round 15
// speedup vs baseline: 1.3231x; 1.0416x over previous
#include <cuda_runtime.h>
#include <cstdint>

#define NN 25000
#define NE 400000
#define FEAT 128
#define HID 64
#define HEADS 4
#define NCLS 2
#define NGRAPH 64
#define SCAN_T 1024
#define SCAN_CH 25   // ceil(NN/SCAN_T)

// ---------------- scratch (device globals; no allocation) ----------------
__device__ alignas(16) float g_xr1 [NN * 64];          // rel-transformed (conv1/conv5)
__device__ alignas(16) float g_acc1[NN * 64];          // root-transform + bias, then +=agg
__device__ alignas(16) float g_xl  [(size_t)NN * 256]; // GAT transformed feats (xl)
__device__ alignas(16) float g_S   [(size_t)NN * 256]; // h2 output (relu'd GAT result)
__device__ alignas(16) float g_as  [NN * 4];
__device__ alignas(16) float g_ad  [NN * 4];
__device__ alignas(16) float g_pool[NGRAPH * HID];
// CSR by destination
__device__ int g_deg[NN];
__device__ int g_off[NN + 1];
__device__ int g_cur[NN];
__device__ int g_esrc[NE];

// ---------------- helpers ----------------
__device__ __forceinline__ float lrelu(float x) { return x > 0.f ? x : 0.2f * x; }

__device__ __forceinline__ unsigned long long packdup(float b) {
    unsigned long long r;
    asm("mov.b64 %0, {%1, %1};" : "=l"(r) : "f"(b));
    return r;
}
__device__ __forceinline__ void ffma2(unsigned long long& acc, unsigned long long a,
                                      unsigned long long b) {
    asm("fma.rn.f32x2 %0, %1, %2, %0;" : "+l"(acc) : "l"(a), "l"(b));
}
__device__ __forceinline__ unsigned long long add2(unsigned long long a, unsigned long long b) {
    unsigned long long r;
    asm("add.rn.f32x2 %0, %1, %2;" : "=l"(r) : "l"(a), "l"(b));
    return r;
}
__device__ __forceinline__ void unpack2(unsigned long long v, float& lo, float& hi) {
    unsigned a, b;
    asm("mov.b64 {%0, %1}, %2;" : "=r"(a), "=r"(b) : "l"(v));
    lo = __uint_as_float(a); hi = __uint_as_float(b);
}

// ============ 128x128-tile SGEMM, f32x2 pairs along N, crossbar-balanced ============
// Per thread: 8 rows x 8 cols (4 f32x2 col-pairs), SMEM double-buffer + reg prefetch.
// Split mode (B1 != null): B = [B0 | B1] each K x 64 (stride ldb); cols 0..63 -> C0,
//   cols 64..127 -> C1 (+bias1), both stride ldc.
// Contiguous mode (B1 == null): B0 is K x N (ldb); col block = blockIdx.x.
// Optional fused attention epilogue (attS != null, contiguous mode): writes
//   g_as/g_ad[row*4 + head] from the accumulator fragments (heads = 64-col groups).
__global__ __launch_bounds__(256, 2)
void gemm128_kernel(const float* __restrict__ A, int lda, int K,
                    const float* __restrict__ B0, const float* __restrict__ B1, int ldb,
                    float* __restrict__ C0, float* __restrict__ C1, int ldc,
                    int M, const float* __restrict__ bias1, int reluA,
                    const float* __restrict__ attS, const float* __restrict__ attD)
{
    __shared__ alignas(16) float As[2][16][132];   // transposed A tile: As[buf][k][row]
    __shared__ alignas(16) float Bs[2][16][128];

    int tid = threadIdx.x;
    int row0 = blockIdx.y * 128;
    int col0 = blockIdx.x * 128;
    int ty = tid >> 4, tx = tid & 15;

    int ar = tid >> 1;                    // A tile row 0..127
    int ak = (tid & 1) * 8;               // A k-offset 0 or 8
    int bk = tid >> 4;                    // B tile k-row 0..15
    int bc = (tid & 15) * 8;              // B tile col 0..120

    int r = row0 + ar;
    bool aValid = (r < M);
    const float* aPtr = A + (size_t)(aValid ? r : 0) * lda + ak;
    const float* bPtr;
    if (B1) bPtr = (bc < 64) ? (B0 + (size_t)bk * ldb + bc)
                             : (B1 + (size_t)bk * ldb + bc - 64);
    else    bPtr = B0 + (size_t)bk * ldb + col0 + bc;
    size_t bStep = (size_t)16 * ldb;

    unsigned long long acc[8][4];
#pragma unroll
    for (int i = 0; i < 8; i++)
#pragma unroll
        for (int j = 0; j < 4; j++) acc[i][j] = 0ULL;

    float av[8], bv[8];
    // ---- prologue: tile 0 ----
    {
        float4 t0 = *(const float4*)aPtr;
        float4 t1 = *(const float4*)(aPtr + 4);
        av[0]=t0.x; av[1]=t0.y; av[2]=t0.z; av[3]=t0.w;
        av[4]=t1.x; av[5]=t1.y; av[6]=t1.z; av[7]=t1.w;
        float4 u0 = *(const float4*)bPtr;
        float4 u1 = *(const float4*)(bPtr + 4);
        bv[0]=u0.x; bv[1]=u0.y; bv[2]=u0.z; bv[3]=u0.w;
        bv[4]=u1.x; bv[5]=u1.y; bv[6]=u1.z; bv[7]=u1.w;
    }
    if (!aValid) {
#pragma unroll
        for (int j = 0; j < 8; j++) av[j] = 0.f;
    }
    if (reluA) {
#pragma unroll
        for (int j = 0; j < 8; j++) av[j] = fmaxf(av[j], 0.f);
    }
#pragma unroll
    for (int j = 0; j < 8; j++) As[0][ak + j][ar] = av[j];
    *(float4*)&Bs[0][bk][bc]     = make_float4(bv[0], bv[1], bv[2], bv[3]);
    *(float4*)&Bs[0][bk][bc + 4] = make_float4(bv[4], bv[5], bv[6], bv[7]);
    __syncthreads();

    int T = K >> 4;
    for (int t = 0; t < T; t++) {
        int cur = t & 1, nxt = cur ^ 1;
        bool more = (t + 1 < T);
        // ---- GMEM loads for next tile ----
        if (more) {
            const float* ap = aPtr + (t + 1) * 16;
            float4 t0 = *(const float4*)ap;
            float4 t1 = *(const float4*)(ap + 4);
            av[0]=t0.x; av[1]=t0.y; av[2]=t0.z; av[3]=t0.w;
            av[4]=t1.x; av[5]=t1.y; av[6]=t1.z; av[7]=t1.w;
            const float* bp = bPtr + (size_t)(t + 1) * bStep;
            float4 u0 = *(const float4*)bp;
            float4 u1 = *(const float4*)(bp + 4);
            bv[0]=u0.x; bv[1]=u0.y; bv[2]=u0.z; bv[3]=u0.w;
            bv[4]=u1.x; bv[5]=u1.y; bv[6]=u1.z; bv[7]=u1.w;
        }

        // ---- k-loop with register fragment prefetch ----
        ulonglong2 fb0 = *(const ulonglong2*)&Bs[cur][0][tx * 8];
        ulonglong2 fb1 = *(const ulonglong2*)&Bs[cur][0][tx * 8 + 4];
        float4     fa0 = *(const float4*)&As[cur][0][ty * 8];
        float4     fa1 = *(const float4*)&As[cur][0][ty * 8 + 4];
#pragma unroll
        for (int k = 0; k < 16; k++) {
            ulonglong2 nb0, nb1; float4 na0, na1;
            if (k < 15) {
                nb0 = *(const ulonglong2*)&Bs[cur][k + 1][tx * 8];
                nb1 = *(const ulonglong2*)&Bs[cur][k + 1][tx * 8 + 4];
                na0 = *(const float4*)&As[cur][k + 1][ty * 8];
                na1 = *(const float4*)&As[cur][k + 1][ty * 8 + 4];
            }
            unsigned long long b2[4] = {fb0.x, fb0.y, fb1.x, fb1.y};
            unsigned long long a2[8];
            a2[0] = packdup(fa0.x); a2[1] = packdup(fa0.y);
            a2[2] = packdup(fa0.z); a2[3] = packdup(fa0.w);
            a2[4] = packdup(fa1.x); a2[5] = packdup(fa1.y);
            a2[6] = packdup(fa1.z); a2[7] = packdup(fa1.w);
#pragma unroll
            for (int rr = 0; rr < 8; rr++)
#pragma unroll
                for (int p = 0; p < 4; p++)
                    ffma2(acc[rr][p], a2[rr], b2[p]);
            if (k < 15) { fb0 = nb0; fb1 = nb1; fa0 = na0; fa1 = na1; }
        }

        // ---- store next tile ----
        if (more) {
            if (!aValid) {
#pragma unroll
                for (int j = 0; j < 8; j++) av[j] = 0.f;
            }
            if (reluA) {
#pragma unroll
                for (int j = 0; j < 8; j++) av[j] = fmaxf(av[j], 0.f);
            }
#pragma unroll
            for (int j = 0; j < 8; j++) As[nxt][ak + j][ar] = av[j];
            *(float4*)&Bs[nxt][bk][bc]     = make_float4(bv[0], bv[1], bv[2], bv[3]);
            *(float4*)&Bs[nxt][bk][bc + 4] = make_float4(bv[4], bv[5], bv[6], bv[7]);
        }
        __syncthreads();
    }

    // ---- epilogue: acc[r][p] == float2 of cols (base+2p, base+2p+1) ----
    bool toC1 = (C1 != nullptr) && (tx >= 8);
    unsigned long long bp2[4] = {0ULL, 0ULL, 0ULL, 0ULL};
    if (toC1 && bias1) {
#pragma unroll
        for (int p = 0; p < 4; p++) {
            float2 bb = *(const float2*)(bias1 + (tx * 8 - 64) + 2 * p);
            unsigned long long t;
            asm("mov.b64 %0, {%1, %2};" : "=l"(t) : "f"(bb.x), "f"(bb.y));
            bp2[p] = t;
        }
    }
#pragma unroll
    for (int rr = 0; rr < 8; rr++) {
        int orow = row0 + ty * 8 + rr;
        if (orow >= M) continue;
        if (toC1) {
            float* cp = C1 + (size_t)orow * ldc + (tx * 8 - 64);
#pragma unroll
            for (int p = 0; p < 4; p++) {
                unsigned long long v = bias1 ? add2(acc[rr][p], bp2[p]) : acc[rr][p];
                *(float2*)(cp + 2 * p) = *(float2*)&v;
            }
        } else {
            float* cp = C0 + (size_t)orow * ldc + col0 + tx * 8;
#pragma unroll
            for (int p = 0; p < 4; p++)
                *(float2*)(cp + 2 * p) = *(float2*)&acc[rr][p];
        }
    }

    // ---- fused attention dot-products (GAT GEMM only) ----
    if (attS) {
        int cb = col0 + tx * 8;        // global column base; att index == column
        int head = cb >> 6;            // 64-col head group
        float ws[8], wd[8];
#pragma unroll
        for (int j = 0; j < 8; j++) { ws[j] = attS[cb + j]; wd[j] = attD[cb + j]; }
#pragma unroll
        for (int rr = 0; rr < 8; rr++) {
            int orow = row0 + ty * 8 + rr;
            float ls = 0.f, ld = 0.f;
#pragma unroll
            for (int p = 0; p < 4; p++) {
                float lo, hi;
                unpack2(acc[rr][p], lo, hi);
                ls += lo * ws[2 * p] + hi * ws[2 * p + 1];
                ld += lo * wd[2 * p] + hi * wd[2 * p + 1];
            }
            // reduce across the 8-lane column group (lanes don't cross head bounds)
#pragma unroll
            for (int off = 1; off < 8; off <<= 1) {
                ls += __shfl_xor_sync(0xffffffffu, ls, off);
                ld += __shfl_xor_sync(0xffffffffu, ld, off);
            }
            if ((tx & 7) == 0 && orow < M) {
                g_as[orow * 4 + head] = ls;
                g_ad[orow * 4 + head] = ld;
            }
        }
    }
}

// ================= CSR build =================
__global__ void init_kernel()
{
    int t = blockIdx.x * 256 + threadIdx.x;
    if (t < NN) g_deg[t] = 0;
    if (t < NGRAPH * HID) g_pool[t] = 0.f;
}

// 4 edges per thread, int4 loads (NE % 4 == 0)
__global__ void csr_count_kernel(const int* __restrict__ dst)
{
    int t = blockIdx.x * 256 + threadIdx.x;
    int e0 = t * 4;
    if (e0 >= NE) return;
    int4 d4 = *(const int4*)(dst + e0);
    atomicAdd(&g_deg[d4.x], 1);
    atomicAdd(&g_deg[d4.y], 1);
    atomicAdd(&g_deg[d4.z], 1);
    atomicAdd(&g_deg[d4.w], 1);
}

__global__ void csr_scan_kernel()
{
    __shared__ int ssum[SCAN_T];
    int t = threadIdx.x;
    int base = t * SCAN_CH;
    int total = 0;
#pragma unroll
    for (int i = 0; i < SCAN_CH; i++) {
        int idx = base + i;
        if (idx < NN) total += g_deg[idx];
    }
    ssum[t] = total;
    __syncthreads();
    for (int d = 1; d < SCAN_T; d <<= 1) {
        int add = (t >= d) ? ssum[t - d] : 0;
        __syncthreads();
        ssum[t] += add;
        __syncthreads();
    }
    int run = ssum[t] - total;   // exclusive prefix
#pragma unroll
    for (int i = 0; i < SCAN_CH; i++) {
        int idx = base + i;
        if (idx < NN) {
            g_off[idx] = run;
            g_cur[idx] = run;
            run += g_deg[idx];
        }
    }
    if (t == SCAN_T - 1) g_off[NN] = run;
}

// 4 edges per thread, int4 loads, 4 independent atomic chains
__global__ void csr_scatter_kernel(const int* __restrict__ src, const int* __restrict__ dst)
{
    int t = blockIdx.x * 256 + threadIdx.x;
    int e0 = t * 4;
    if (e0 >= NE) return;
    int4 d4 = *(const int4*)(dst + e0);
    int4 s4 = *(const int4*)(src + e0);
    int p0 = atomicAdd(&g_cur[d4.x], 1);
    int p1 = atomicAdd(&g_cur[d4.y], 1);
    int p2 = atomicAdd(&g_cur[d4.z], 1);
    int p3 = atomicAdd(&g_cur[d4.w], 1);
    g_esrc[p0] = s4.x;
    g_esrc[p1] = s4.y;
    g_esrc[p2] = s4.z;
    g_esrc[p3] = s4.w;
}

// ---------------- conv gather: g_acc1[d] += sum_{s->d} g_xr1[s]  (64-dim, no atomics) ----
__global__ __launch_bounds__(256)
void conv_gather_kernel()
{
    int half = threadIdx.x >> 4;            // 0..15
    int lane16 = threadIdx.x & 15;
    int d = blockIdx.x * 16 + half;
    if (d >= NN) return;
    int beg = g_off[d], end = g_off[d + 1];
    float ax = 0.f, ay = 0.f, az = 0.f, aw = 0.f;
    for (int i = beg; i < end; i++) {
        int s = g_esrc[i];                  // broadcast load within half-warp
        float4 v = *(const float4*)(g_xr1 + (size_t)s * 64 + lane16 * 4);
        ax += v.x; ay += v.y; az += v.z; aw += v.w;
    }
    float* p = g_acc1 + (size_t)d * 64 + lane16 * 4;
    float4 o = *(float4*)p;
    o.x += ax; o.y += ay; o.z += az; o.w += aw;
    *(float4*)p = o;
}

// ---------------- fused GAT per node: max + softmax + aggregate + bias + relu ----------
__global__ __launch_bounds__(256)
void gat_node_kernel(const float* __restrict__ bg)
{
    int warp = threadIdx.x >> 5, lane = threadIdx.x & 31;
    int d = blockIdx.x * 8 + warp;
    if (d >= NN) return;
    int beg = g_off[d], end = g_off[d + 1];

    float4 ad4 = *(const float4*)(g_ad + d * 4);
    float4 as_d = *(const float4*)(g_as + d * 4);
    float4 sl;   // self-loop logits
    sl.x = lrelu(as_d.x + ad4.x); sl.y = lrelu(as_d.y + ad4.y);
    sl.z = lrelu(as_d.z + ad4.z); sl.w = lrelu(as_d.w + ad4.w);

    // ---- pass 1: per-head max over in-edges (+self) ----
    float4 m4 = sl;
    for (int i = beg + lane; i < end; i += 32) {
        int s = g_esrc[i];
        float4 a4 = *(const float4*)(g_as + s * 4);
        m4.x = fmaxf(m4.x, lrelu(a4.x + ad4.x));
        m4.y = fmaxf(m4.y, lrelu(a4.y + ad4.y));
        m4.z = fmaxf(m4.z, lrelu(a4.z + ad4.z));
        m4.w = fmaxf(m4.w, lrelu(a4.w + ad4.w));
    }
#pragma unroll
    for (int off = 16; off; off >>= 1) {
        m4.x = fmaxf(m4.x, __shfl_xor_sync(0xffffffffu, m4.x, off));
        m4.y = fmaxf(m4.y, __shfl_xor_sync(0xffffffffu, m4.y, off));
        m4.z = fmaxf(m4.z, __shfl_xor_sync(0xffffffffu, m4.z, off));
        m4.w = fmaxf(m4.w, __shfl_xor_sync(0xffffffffu, m4.w, off));
    }

    // ---- pass 2: accumulate p*xl ----
    int hsel = lane >> 4;    // 0 -> heads 0/2 ; 1 -> heads 1/3
    float4 acc0, acc1, den;
    {
        float px = expf(sl.x - m4.x), py = expf(sl.y - m4.y);
        float pz = expf(sl.z - m4.z), pw = expf(sl.w - m4.w);
        den = make_float4(px, py, pz, pw);
        const float* xp = g_xl + (size_t)d * 256;
        float4 v0 = *(const float4*)(xp + lane * 4);
        float4 v1 = *(const float4*)(xp + 128 + lane * 4);
        float q0 = hsel ? py : px;
        float q1 = hsel ? pw : pz;
        acc0 = make_float4(q0 * v0.x, q0 * v0.y, q0 * v0.z, q0 * v0.w);
        acc1 = make_float4(q1 * v1.x, q1 * v1.y, q1 * v1.z, q1 * v1.w);
    }

    for (int i0 = beg; i0 < end; i0 += 32) {
        int i = i0 + lane;
        int s = 0; float px = 0.f, py = 0.f, pz = 0.f, pw = 0.f;
        if (i < end) {
            s = g_esrc[i];
            float4 a4 = *(const float4*)(g_as + s * 4);
            px = expf(lrelu(a4.x + ad4.x) - m4.x);
            py = expf(lrelu(a4.y + ad4.y) - m4.y);
            pz = expf(lrelu(a4.z + ad4.z) - m4.z);
            pw = expf(lrelu(a4.w + ad4.w) - m4.w);
        }
        int cnt = end - i0; if (cnt > 32) cnt = 32;
        for (int j = 0; j < cnt; j++) {
            int   sj = __shfl_sync(0xffffffffu, s, j);
            float qx = __shfl_sync(0xffffffffu, px, j);
            float qy = __shfl_sync(0xffffffffu, py, j);
            float qz = __shfl_sync(0xffffffffu, pz, j);
            float qw = __shfl_sync(0xffffffffu, pw, j);
            den.x += qx; den.y += qy; den.z += qz; den.w += qw;
            const float* xp = g_xl + (size_t)sj * 256;
            float4 v0 = *(const float4*)(xp + lane * 4);
            float4 v1 = *(const float4*)(xp + 128 + lane * 4);
            float q0 = hsel ? qy : qx;
            float q1 = hsel ? qw : qz;
            acc0.x += q0 * v0.x; acc0.y += q0 * v0.y; acc0.z += q0 * v0.z; acc0.w += q0 * v0.w;
            acc1.x += q1 * v1.x; acc1.y += q1 * v1.y; acc1.z += q1 * v1.z; acc1.w += q1 * v1.w;
        }
    }

    float d0 = hsel ? den.y : den.x;
    float d1 = hsel ? den.w : den.z;
    float4 b0 = *(const float4*)(bg + lane * 4);
    float4 b1 = *(const float4*)(bg + 128 + lane * 4);
    float inv0 = 1.f / d0, inv1 = 1.f / d1;
    float4 o0, o1;
    o0.x = fmaxf(acc0.x * inv0 + b0.x, 0.f); o0.y = fmaxf(acc0.y * inv0 + b0.y, 0.f);
    o0.z = fmaxf(acc0.z * inv0 + b0.z, 0.f); o0.w = fmaxf(acc0.w * inv0 + b0.w, 0.f);
    o1.x = fmaxf(acc1.x * inv1 + b1.x, 0.f); o1.y = fmaxf(acc1.y * inv1 + b1.y, 0.f);
    o1.z = fmaxf(acc1.z * inv1 + b1.z, 0.f); o1.w = fmaxf(acc1.w * inv1 + b1.w, 0.f);
    float* op = g_S + (size_t)d * 256;
    *(float4*)(op + lane * 4) = o0;
    *(float4*)(op + 128 + lane * 4) = o1;
}

// ---------------- pooling: g_pool[batch[n]] += relu(acc5[n])  (batch sorted) ----------------
__global__ void pool_kernel(const int* __restrict__ batch)
{
    int d = threadIdx.x & 63;
    int sub = threadIdx.x >> 6;
    int n0 = blockIdx.x * 64 + sub * 16;
    float sum = 0.f; int cur = -1;
#pragma unroll
    for (int i = 0; i < 16; i++) {
        int n = n0 + i;
        if (n >= NN) break;
        int b = batch[n];
        if (b != cur) {
            if (cur >= 0) atomicAdd(&g_pool[cur * 64 + d], sum);
            cur = b; sum = 0.f;
        }
        sum += fmaxf(g_acc1[(size_t)n * 64 + d], 0.f);
    }
    if (cur >= 0) atomicAdd(&g_pool[cur * 64 + d], sum);
}

// ---------------- head ----------------
__global__ void head_kernel(const float* __restrict__ Wfc1, const float* __restrict__ bfc1,
                            const float* __restrict__ Wfc2, const float* __restrict__ bfc2,
                            float* __restrict__ out)
{
    __shared__ float sg[64 * 64];
    __shared__ float sw[64 * 64];
    int t = threadIdx.x;
    for (int i = t; i < 4096; i += 256) { sg[i] = g_pool[i]; sw[i] = Wfc1[i]; }
    __syncthreads();
    float r[16];
#pragma unroll
    for (int i = 0; i < 16; i++) {
        int idx = t + 256 * i;
        int rr = idx >> 6, cc = idx & 63;
        float s = bfc1[cc];
#pragma unroll
        for (int k = 0; k < 64; k++) s += sg[rr * 64 + k] * sw[k * 64 + cc];
        r[i] = fmaxf(s, 0.f);
    }
    __syncthreads();
#pragma unroll
    for (int i = 0; i < 16; i++) sg[t + 256 * i] = r[i];
    __syncthreads();
    if (t < 128) {
        int rr = t >> 1, cc = t & 1;
        float s = bfc2[cc];
#pragma unroll
        for (int k = 0; k < 64; k++) s += sg[rr * 64 + k] * Wfc2[k * 2 + cc];
        out[t] = 1.f / (1.f + expf(-s));
    }
}

// ---------------- launch ----------------
extern "C" void kernel_launch(void* const* d_in, const int* in_sizes, int n_in,
                              void* d_out, int out_size)
{
    const float* x       = (const float*)d_in[0];
    const int*   ei      = (const int*)d_in[1];
    const int*   batch   = (const int*)d_in[2];
    const float* W1_rel  = (const float*)d_in[3];
    const float* b1      = (const float*)d_in[4];
    const float* W1_root = (const float*)d_in[5];
    const float* Wg      = (const float*)d_in[6];
    const float* att_src = (const float*)d_in[7];
    const float* att_dst = (const float*)d_in[8];
    const float* bg      = (const float*)d_in[9];
    const float* W5_rel  = (const float*)d_in[10];
    const float* b5      = (const float*)d_in[11];
    const float* W5_root = (const float*)d_in[12];
    const float* W_fc1   = (const float*)d_in[13];
    const float* b_fc1   = (const float*)d_in[14];
    const float* W_fc2   = (const float*)d_in[15];
    const float* b_fc2   = (const float*)d_in[16];
    float* out = (float*)d_out;

    const int* src = ei;
    const int* dst = ei + NE;

    static float *p_xr1 = nullptr, *p_acc1 = nullptr, *p_xl = nullptr, *p_S = nullptr;
    if (!p_xr1) {
        cudaGetSymbolAddress((void**)&p_xr1, g_xr1);
        cudaGetSymbolAddress((void**)&p_acc1, g_acc1);
        cudaGetSymbolAddress((void**)&p_xl, g_xl);
        cudaGetSymbolAddress((void**)&p_S, g_S);
    }

    const int GY = (NN + 127) / 128;   // 196

    // CSR build
    init_kernel<<<(NN + 255) / 256, 256>>>();
    csr_count_kernel<<<(NE / 4 + 255) / 256, 256>>>(dst);
    csr_scan_kernel<<<1, SCAN_T>>>();
    csr_scatter_kernel<<<(NE / 4 + 255) / 256, 256>>>(src, dst);

    // conv1 fused: [xr1 | acc1] = x @ [W1_rel | W1_root(+b1)]
    gemm128_kernel<<<dim3(1, GY), 256>>>(x, FEAT, FEAT, W1_rel, W1_root, 64,
                                         p_xr1, p_acc1, 64, NN, b1, 0, nullptr, nullptr);
    conv_gather_kernel<<<(NN + 15) / 16, 256>>>();

    // GAT: xl = relu(h1) @ Wg   (N=256, contiguous) + fused a_s/a_d epilogue
    gemm128_kernel<<<dim3(2, GY), 256>>>(p_acc1, 64, 64, Wg, nullptr, 256,
                                         p_xl, nullptr, 256, NN, nullptr, 1,
                                         att_src, att_dst);
    gat_node_kernel<<<(NN + 7) / 8, 256>>>(bg);

    // conv5 fused: [xr5 | acc5] = h2 @ [W5_rel | W5_root(+b5)]  (h2 lives in g_S)
    gemm128_kernel<<<dim3(1, GY), 256>>>(p_S, 256, 256, W5_rel, W5_root, 64,
                                         p_xr1, p_acc1, 64, NN, b5, 0, nullptr, nullptr);
    conv_gather_kernel<<<(NN + 15) / 16, 256>>>();

    // pool + head
    pool_kernel<<<(NN + 63) / 64, 256>>>(batch);
    head_kernel<<<1, 256>>>(W_fc1, b_fc1, W_fc2, b_fc2, out);
}